// round 1
// baseline (speedup 1.0000x reference)
#include <cuda_runtime.h>
#include <math.h>

#define BB 32
#define QQ 40
#define LL 1024
#define HH 1024
#define M2Q 80            // 2*Q rows per batch in pooling GEMM
#define MIN_SIG (1.0f/4096.0f)
// 0.5 * log(max(L*min_sig*4, 1+1e-6)) = 0.5*log(1.000001)
#define HALF_LOG_RANGE 4.9999975e-07f
#define MAX_DELTA_C 0.1f

// -------- device scratch (static; no runtime allocation) --------
__device__ float g_W[BB * M2Q * LL];        // gaussian weights, rows m=2q+s
__device__ float g_pool[BB * M2Q * HH];     // pooled feats, (b,q,s,h) contiguous => J rows of 2048
__device__ float g_hidden[BB * QQ * HH];    // relu hidden
__device__ float g_state[BB * QQ * 2];      // start,end per (b,q)
__device__ float g_txtoff[BB * 2];          // txt offsets
__device__ float g_txtctrb[BB * HH];        // txt part of mlp0 + bias

// ---------------- txt offset: tanh(txt_rep @ txt_proj_w + b) * 0.5*log_range ----------------
__global__ void k_txt_off(const float* __restrict__ txt_rep,
                          const float* __restrict__ tpw,
                          const float* __restrict__ tpb) {
    int b = blockIdx.x, t = threadIdx.x;
    float a0 = 0.f, a1 = 0.f;
    for (int h = t; h < HH; h += 256) {
        float x = txt_rep[b * HH + h];
        a0 += x * tpw[h * 2 + 0];
        a1 += x * tpw[h * 2 + 1];
    }
    __shared__ float s0[256], s1[256];
    s0[t] = a0; s1[t] = a1; __syncthreads();
    for (int ofs = 128; ofs > 0; ofs >>= 1) {
        if (t < ofs) { s0[t] += s0[t + ofs]; s1[t] += s1[t + ofs]; }
        __syncthreads();
    }
    if (t == 0) {
        g_txtoff[b * 2 + 0] = tanhf(s0[0] + tpb[0]) * HALF_LOG_RANGE;
        g_txtoff[b * 2 + 1] = tanhf(s1[0] + tpb[1]) * HALF_LOG_RANGE;
    }
}

// ---------------- txt contribution to mlp0: txt_rep @ mlp0_w[2H:3H] + mlp0_b ----------------
__global__ void k_txt_ctrb(const float* __restrict__ txt_rep,
                           const float* __restrict__ m0w,
                           const float* __restrict__ m0b) {
    int b = blockIdx.y;
    int h = blockIdx.x * 256 + threadIdx.x;
    float acc = m0b[h];
    const float* wp = m0w + (size_t)2 * HH * HH + h;
    const float* xr = txt_rep + (size_t)b * HH;
#pragma unroll 4
    for (int k = 0; k < HH; k++) acc += xr[k] * wp[(size_t)k * HH];
    g_txtctrb[b * HH + h] = acc;
}

// ---------------- init start/end from pred_spans ----------------
__global__ void k_init(const float* __restrict__ pred) {
    int r = blockIdx.x * blockDim.x + threadIdx.x;
    if (r < BB * QQ) {
        float c = pred[r * 2 + 0], w = pred[r * 2 + 1];
        float s = fminf(fmaxf(c - 0.5f * w, 0.f), 1.f);
        float e = fminf(fmaxf(c + 0.5f * w, 0.f), 1.f);
        g_state[r * 2 + 0] = s;
        g_state[r * 2 + 1] = e;
    }
}

// ---------------- gaussian weights (normalized) ----------------
__global__ void k_weights(const float* __restrict__ vid_mask,
                          const float* __restrict__ ls_p, const float* __restrict__ le_p,
                          const float* __restrict__ sws_p, const float* __restrict__ swe_p) {
    int r = blockIdx.x;        // b*Q + q
    int b = r / QQ;
    int t = threadIdx.x;
    float s = g_state[r * 2 + 0], e = g_state[r * 2 + 1];
    float width = fmaxf(e - s, 1e-6f);
    float sig_s = fmaxf(expf(ls_p[0] + sws_p[0] * width + g_txtoff[b * 2 + 0]), MIN_SIG);
    float sig_e = fmaxf(expf(le_p[0] + swe_p[0] * width + g_txtoff[b * 2 + 1]), MIN_SIG);
    float inv_ss = 1.0f / sig_s, inv_se = 1.0f / sig_e;

    const float* mrow = vid_mask + (size_t)b * LL;
    float ws[4], we[4];
    float sum_s = 0.f, sum_e = 0.f;
#pragma unroll
    for (int i = 0; i < 4; i++) {
        int l = t + i * 256;
        float tp = (float)l * (1.0f / 1023.0f);
        float m = mrow[l];
        float ds = (tp - s) * inv_ss;
        float vs = expf(-0.5f * ds * ds) * m;
        float de = (tp - e) * inv_se;
        float ve = expf(-0.5f * de * de) * m;
        ws[i] = vs; we[i] = ve;
        sum_s += vs; sum_e += ve;
    }
    __shared__ float r0[256], r1[256];
    r0[t] = sum_s; r1[t] = sum_e; __syncthreads();
    for (int ofs = 128; ofs > 0; ofs >>= 1) {
        if (t < ofs) { r0[t] += r0[t + ofs]; r1[t] += r1[t + ofs]; }
        __syncthreads();
    }
    float is = 1.0f / fmaxf(r0[0], 1e-8f);
    float ie = 1.0f / fmaxf(r1[0], 1e-8f);
    float* wrow_s = g_W + (size_t)(r * 2 + 0) * LL;
    float* wrow_e = g_W + (size_t)(r * 2 + 1) * LL;
#pragma unroll
    for (int i = 0; i < 4; i++) {
        int l = t + i * 256;
        wrow_s[l] = ws[i] * is;
        wrow_e[l] = we[i] * ie;
    }
}

// ---------------- pooling GEMM: per batch C(80,1024) = W(80,1024) @ vid(1024,1024) ----------------
// BM=80, BN=128, BK=32, 256 threads (16x16), micro-tile 5x8
__global__ void __launch_bounds__(256) k_pool(const float* __restrict__ vid_feat) {
    int b = blockIdx.y;
    int n0 = blockIdx.x * 128;
    const float* A  = g_W   + (size_t)b * M2Q * LL;
    const float* Bv = vid_feat + (size_t)b * LL * HH;
    float* C        = g_pool + (size_t)b * M2Q * HH;

    __shared__ float As[32 * 81];
    __shared__ float Bs[32 * 128];

    int t = threadIdx.x;
    int tx = t & 15, ty = t >> 4;
    float acc[5][8];
#pragma unroll
    for (int i = 0; i < 5; i++)
#pragma unroll
        for (int j = 0; j < 8; j++) acc[i][j] = 0.f;

    for (int k0 = 0; k0 < LL; k0 += 32) {
        for (int idx = t; idx < 80 * 32; idx += 256) {
            int m = idx >> 5, k = idx & 31;
            As[k * 81 + m] = A[(size_t)m * LL + k0 + k];
        }
        for (int idx = t; idx < 32 * 32; idx += 256) {
            int k = idx >> 5, n4 = idx & 31;
            float4 v = *reinterpret_cast<const float4*>(Bv + (size_t)(k0 + k) * HH + n0 + n4 * 4);
            *reinterpret_cast<float4*>(&Bs[k * 128 + n4 * 4]) = v;
        }
        __syncthreads();
#pragma unroll
        for (int k = 0; k < 32; k++) {
            float a[5], bb[8];
#pragma unroll
            for (int i = 0; i < 5; i++) a[i] = As[k * 81 + ty + 16 * i];
#pragma unroll
            for (int j = 0; j < 8; j++) bb[j] = Bs[k * 128 + tx + 16 * j];
#pragma unroll
            for (int i = 0; i < 5; i++)
#pragma unroll
                for (int j = 0; j < 8; j++) acc[i][j] += a[i] * bb[j];
        }
        __syncthreads();
    }
#pragma unroll
    for (int i = 0; i < 5; i++) {
        int m = ty + 16 * i;
#pragma unroll
        for (int j = 0; j < 8; j++) {
            int n = n0 + tx + 16 * j;
            C[(size_t)m * HH + n] = acc[i][j];
        }
    }
}

// ---------------- MLP0 GEMM: hidden(1280,1024) = relu(J(1280,2048) @ m0w[0:2048] + txt_ctrb) ----------------
// BM=64, BN=128, BK=32, 256 threads, micro-tile 4x8
__global__ void __launch_bounds__(256) k_mlp0(const float* __restrict__ m0w) {
    int m0 = blockIdx.y * 64;
    int n0 = blockIdx.x * 128;
    const float* J = g_pool;   // (1280, 2048)

    __shared__ float As[32 * 65];
    __shared__ float Bs[32 * 128];

    int t = threadIdx.x;
    int tx = t & 15, ty = t >> 4;
    float acc[4][8];
#pragma unroll
    for (int i = 0; i < 4; i++)
#pragma unroll
        for (int j = 0; j < 8; j++) acc[i][j] = 0.f;

    for (int k0 = 0; k0 < 2048; k0 += 32) {
        for (int idx = t; idx < 64 * 32; idx += 256) {
            int m = idx >> 5, k = idx & 31;
            As[k * 65 + m] = J[(size_t)(m0 + m) * 2048 + k0 + k];
        }
        for (int idx = t; idx < 32 * 32; idx += 256) {
            int k = idx >> 5, n4 = idx & 31;
            float4 v = *reinterpret_cast<const float4*>(m0w + (size_t)(k0 + k) * HH + n0 + n4 * 4);
            *reinterpret_cast<float4*>(&Bs[k * 128 + n4 * 4]) = v;
        }
        __syncthreads();
#pragma unroll
        for (int k = 0; k < 32; k++) {
            float a[4], bb[8];
#pragma unroll
            for (int i = 0; i < 4; i++) a[i] = As[k * 65 + ty + 16 * i];
#pragma unroll
            for (int j = 0; j < 8; j++) bb[j] = Bs[k * 128 + tx + 16 * j];
#pragma unroll
            for (int i = 0; i < 4; i++)
#pragma unroll
                for (int j = 0; j < 8; j++) acc[i][j] += a[i] * bb[j];
        }
        __syncthreads();
    }
#pragma unroll
    for (int i = 0; i < 4; i++) {
        int r = m0 + ty + 16 * i;
        int bidx = r / QQ;
#pragma unroll
        for (int j = 0; j < 8; j++) {
            int h = n0 + tx + 16 * j;
            float v = acc[i][j] + g_txtctrb[bidx * HH + h];
            g_hidden[(size_t)r * HH + h] = fmaxf(v, 0.f);
        }
    }
}

// ---------------- MLP1 + state update + output write ----------------
__global__ void k_mlp1(const float* __restrict__ m1w, const float* __restrict__ m1b,
                       float* __restrict__ out, int pass, int last) {
    int r = blockIdx.x, t = threadIdx.x;
    const float* hrow = g_hidden + (size_t)r * HH;
    float a0 = 0.f, a1 = 0.f;
    for (int h = t; h < HH; h += 256) {
        float x = hrow[h];
        a0 += x * m1w[h * 2 + 0];
        a1 += x * m1w[h * 2 + 1];
    }
    __shared__ float s0[256], s1[256];
    s0[t] = a0; s1[t] = a1; __syncthreads();
    for (int ofs = 128; ofs > 0; ofs >>= 1) {
        if (t < ofs) { s0[t] += s0[t + ofs]; s1[t] += s1[t + ofs]; }
        __syncthreads();
    }
    if (t == 0) {
        float d0 = tanhf(s0[0] + m1b[0]) * MAX_DELTA_C;
        float d1 = tanhf(s1[0] + m1b[1]) * MAX_DELTA_C;
        float s = fminf(fmaxf(g_state[r * 2 + 0] + d0, 0.f), 1.f);
        float e = fminf(fmaxf(g_state[r * 2 + 1] + d1, 0.f), 1.f);
        g_state[r * 2 + 0] = s;
        g_state[r * 2 + 1] = e;
        float c = 0.5f * (s + e);
        float w = fmaxf(e - s, 1e-6f);
        // second tuple element: stacked passes at offset B*Q*2, pass p at p*B*Q*2
        int base = (1 + pass) * BB * QQ * 2;
        out[base + r * 2 + 0] = c;
        out[base + r * 2 + 1] = w;
        if (pass == last) {   // first tuple element: passes[-1]
            out[r * 2 + 0] = c;
            out[r * 2 + 1] = w;
        }
    }
}

extern "C" void kernel_launch(void* const* d_in, const int* in_sizes, int n_in,
                              void* d_out, int out_size) {
    const float* pred = (const float*)d_in[0];   // (B,Q,2)
    const float* vid  = (const float*)d_in[1];   // (B,L,H)
    const float* mask = (const float*)d_in[2];   // (B,L)
    const float* txt  = (const float*)d_in[3];   // (B,H)
    const float* ls   = (const float*)d_in[4];
    const float* le   = (const float*)d_in[5];
    const float* sws  = (const float*)d_in[6];
    const float* swe  = (const float*)d_in[7];
    const float* tpw  = (const float*)d_in[8];   // (H,2)
    const float* tpb  = (const float*)d_in[9];   // (2,)
    const float* m0w  = (const float*)d_in[10];  // (3H,H)
    const float* m0b  = (const float*)d_in[11];  // (H,)
    const float* m1w  = (const float*)d_in[12];  // (H,2)
    const float* m1b  = (const float*)d_in[13];  // (2,)
    float* out = (float*)d_out;

    k_txt_off<<<BB, 256>>>(txt, tpw, tpb);
    k_txt_ctrb<<<dim3(HH / 256, BB), 256>>>(txt, m0w, m0b);
    k_init<<<(BB * QQ + 255) / 256, 256>>>(pred);

    for (int p = 0; p < 2; p++) {
        k_weights<<<BB * QQ, 256>>>(mask, ls, le, sws, swe);
        k_pool<<<dim3(HH / 128, BB), 256>>>(vid);
        k_mlp0<<<dim3(HH / 128, (BB * QQ) / 64), 256>>>(m0w);
        k_mlp1<<<BB * QQ, 256>>>(m1w, m1b, out, p, 1);
    }
}

// round 2
// speedup vs baseline: 2.4116x; 2.4116x over previous
#include <cuda_runtime.h>
#include <cuda_bf16.h>
#include <math.h>
#include <stdint.h>

#define BB 32
#define QQ 40
#define LL 1024
#define HH 1024
#define MIN_SIG (1.0f/4096.0f)
#define HALF_LOG_RANGE 4.9999975e-07f
#define MAX_DELTA_C 0.1f

// -------- device scratch (static; no runtime allocation) --------
__device__ __nv_bfloat16 g_vid_hi[BB * LL * HH];
__device__ __nv_bfloat16 g_vid_lo[BB * LL * HH];
__device__ __nv_bfloat16 g_w0_hi[2 * HH * HH];
__device__ __nv_bfloat16 g_w0_lo[2 * HH * HH];
__device__ __nv_bfloat16 g_W_hi[BB * 80 * LL];
__device__ __nv_bfloat16 g_W_lo[BB * 80 * LL];
__device__ __nv_bfloat16 g_J_hi[BB * QQ * 2 * HH];   // joint (1280, 2048)
__device__ __nv_bfloat16 g_J_lo[BB * QQ * 2 * HH];
__device__ float g_hidden[BB * QQ * HH];
__device__ float g_state[BB * QQ * 2];
__device__ float g_txtoff[BB * 2];
__device__ float g_txtctrb[BB * HH];

// ---------------- helpers ----------------
__device__ __forceinline__ void bsplit(float v, __nv_bfloat16& h, __nv_bfloat16& l) {
    h = __float2bfloat16(v);
    l = __float2bfloat16(v - __bfloat162float(h));
}

__device__ __forceinline__ uint32_t s2u(const void* p) {
    return (uint32_t)__cvta_generic_to_shared(p);
}

__device__ __forceinline__ void ldsm4(uint32_t addr, uint32_t* r) {
    asm volatile("ldmatrix.sync.aligned.m8n8.x4.shared.b16 {%0,%1,%2,%3}, [%4];"
        : "=r"(r[0]), "=r"(r[1]), "=r"(r[2]), "=r"(r[3]) : "r"(addr));
}
__device__ __forceinline__ void ldsm4t(uint32_t addr, uint32_t* r01, uint32_t* r23) {
    asm volatile("ldmatrix.sync.aligned.m8n8.x4.trans.shared.b16 {%0,%1,%2,%3}, [%4];"
        : "=r"(r01[0]), "=r"(r01[1]), "=r"(r23[0]), "=r"(r23[1]) : "r"(addr));
}

#define MMA(c, a, b) asm volatile( \
    "mma.sync.aligned.m16n8k16.row.col.f32.bf16.bf16.f32 " \
    "{%0,%1,%2,%3}, {%4,%5,%6,%7}, {%8,%9}, {%0,%1,%2,%3};\n" \
    : "+f"((c)[0]), "+f"((c)[1]), "+f"((c)[2]), "+f"((c)[3]) \
    : "r"((a)[0]), "r"((a)[1]), "r"((a)[2]), "r"((a)[3]), \
      "r"((b)[0]), "r"((b)[1]))

// ---------------- conversion kernels (once per launch) ----------------
__global__ void k_cvt_vid(const float* __restrict__ src) {
    int i = blockIdx.x * 256 + threadIdx.x;          // one float4 per thread
    float4 v = ((const float4*)src)[i];
    __nv_bfloat16 h0, h1, h2, h3, l0, l1, l2, l3;
    bsplit(v.x, h0, l0); bsplit(v.y, h1, l1);
    bsplit(v.z, h2, l2); bsplit(v.w, h3, l3);
    __nv_bfloat162* H = (__nv_bfloat162*)g_vid_hi;
    __nv_bfloat162* L = (__nv_bfloat162*)g_vid_lo;
    __nv_bfloat162 a; a.x = h0; a.y = h1;
    __nv_bfloat162 b; b.x = h2; b.y = h3;
    H[2 * i] = a; H[2 * i + 1] = b;
    a.x = l0; a.y = l1; b.x = l2; b.y = l3;
    L[2 * i] = a; L[2 * i + 1] = b;
}

__global__ void k_cvt_w0(const float* __restrict__ src) {
    int i = blockIdx.x * 256 + threadIdx.x;
    float4 v = ((const float4*)src)[i];
    __nv_bfloat16 h0, h1, h2, h3, l0, l1, l2, l3;
    bsplit(v.x, h0, l0); bsplit(v.y, h1, l1);
    bsplit(v.z, h2, l2); bsplit(v.w, h3, l3);
    __nv_bfloat162* H = (__nv_bfloat162*)g_w0_hi;
    __nv_bfloat162* L = (__nv_bfloat162*)g_w0_lo;
    __nv_bfloat162 a; a.x = h0; a.y = h1;
    __nv_bfloat162 b; b.x = h2; b.y = h3;
    H[2 * i] = a; H[2 * i + 1] = b;
    a.x = l0; a.y = l1; b.x = l2; b.y = l3;
    L[2 * i] = a; L[2 * i + 1] = b;
}

// ---------------- txt offset ----------------
__global__ void k_txt_off(const float* __restrict__ txt_rep,
                          const float* __restrict__ tpw,
                          const float* __restrict__ tpb) {
    int b = blockIdx.x, t = threadIdx.x;
    float a0 = 0.f, a1 = 0.f;
    for (int h = t; h < HH; h += 256) {
        float x = txt_rep[b * HH + h];
        a0 += x * tpw[h * 2 + 0];
        a1 += x * tpw[h * 2 + 1];
    }
    __shared__ float s0[256], s1[256];
    s0[t] = a0; s1[t] = a1; __syncthreads();
    for (int ofs = 128; ofs > 0; ofs >>= 1) {
        if (t < ofs) { s0[t] += s0[t + ofs]; s1[t] += s1[t + ofs]; }
        __syncthreads();
    }
    if (t == 0) {
        g_txtoff[b * 2 + 0] = tanhf(s0[0] + tpb[0]) * HALF_LOG_RANGE;
        g_txtoff[b * 2 + 1] = tanhf(s1[0] + tpb[1]) * HALF_LOG_RANGE;
    }
}

// ---------------- txt contribution to mlp0 ----------------
__global__ void k_txt_ctrb(const float* __restrict__ txt_rep,
                           const float* __restrict__ m0w,
                           const float* __restrict__ m0b) {
    int b = blockIdx.y;
    int h = blockIdx.x * 256 + threadIdx.x;
    float acc = m0b[h];
    const float* wp = m0w + (size_t)2 * HH * HH + h;
    const float* xr = txt_rep + (size_t)b * HH;
#pragma unroll 4
    for (int k = 0; k < HH; k++) acc += xr[k] * wp[(size_t)k * HH];
    g_txtctrb[b * HH + h] = acc;
}

// ---------------- init start/end ----------------
__global__ void k_init(const float* __restrict__ pred) {
    int r = blockIdx.x * blockDim.x + threadIdx.x;
    if (r < BB * QQ) {
        float c = pred[r * 2 + 0], w = pred[r * 2 + 1];
        g_state[r * 2 + 0] = fminf(fmaxf(c - 0.5f * w, 0.f), 1.f);
        g_state[r * 2 + 1] = fminf(fmaxf(c + 0.5f * w, 0.f), 1.f);
    }
}

// ---------------- gaussian weights -> bf16 hi/lo ----------------
__global__ void k_weights(const float* __restrict__ vid_mask,
                          const float* __restrict__ ls_p, const float* __restrict__ le_p,
                          const float* __restrict__ sws_p, const float* __restrict__ swe_p) {
    int r = blockIdx.x;        // b*Q + q
    int b = r / QQ;
    int t = threadIdx.x;
    float s = g_state[r * 2 + 0], e = g_state[r * 2 + 1];
    float width = fmaxf(e - s, 1e-6f);
    float sig_s = fmaxf(expf(ls_p[0] + sws_p[0] * width + g_txtoff[b * 2 + 0]), MIN_SIG);
    float sig_e = fmaxf(expf(le_p[0] + swe_p[0] * width + g_txtoff[b * 2 + 1]), MIN_SIG);
    float inv_ss = 1.0f / sig_s, inv_se = 1.0f / sig_e;

    const float* mrow = vid_mask + (size_t)b * LL;
    float ws[4], we[4];
    float sum_s = 0.f, sum_e = 0.f;
#pragma unroll
    for (int i = 0; i < 4; i++) {
        int l = t + i * 256;
        float tp = (float)l * (1.0f / 1023.0f);
        float m = mrow[l];
        float ds = (tp - s) * inv_ss;
        float vs = expf(-0.5f * ds * ds) * m;
        float de = (tp - e) * inv_se;
        float ve = expf(-0.5f * de * de) * m;
        ws[i] = vs; we[i] = ve;
        sum_s += vs; sum_e += ve;
    }
    __shared__ float r0[256], r1[256];
    r0[t] = sum_s; r1[t] = sum_e; __syncthreads();
    for (int ofs = 128; ofs > 0; ofs >>= 1) {
        if (t < ofs) { r0[t] += r0[t + ofs]; r1[t] += r1[t + ofs]; }
        __syncthreads();
    }
    float is = 1.0f / fmaxf(r0[0], 1e-8f);
    float ie = 1.0f / fmaxf(r1[0], 1e-8f);
    size_t rs = (size_t)(r * 2 + 0) * LL;
    size_t re = (size_t)(r * 2 + 1) * LL;
#pragma unroll
    for (int i = 0; i < 4; i++) {
        int l = t + i * 256;
        __nv_bfloat16 h, lo;
        bsplit(ws[i] * is, h, lo);
        g_W_hi[rs + l] = h; g_W_lo[rs + l] = lo;
        bsplit(we[i] * ie, h, lo);
        g_W_hi[re + l] = h; g_W_lo[re + l] = lo;
    }
}

// ---------------- pool GEMM (tensor): per batch C(80,1024)=W(80,1024)@V(1024,1024) ----------------
// BM=128 (80 valid), BN=128, BK=32. 8 warps as 4x2; warp tile 32x64.
__global__ void __launch_bounds__(256, 1) k_pool_mma() {
    int b  = blockIdx.y;
    int n0 = blockIdx.x * 128;
    const __nv_bfloat16* Ah = g_W_hi + (size_t)b * 80 * LL;
    const __nv_bfloat16* Al = g_W_lo + (size_t)b * 80 * LL;
    const __nv_bfloat16* Bh = g_vid_hi + (size_t)b * LL * HH;
    const __nv_bfloat16* Bl = g_vid_lo + (size_t)b * LL * HH;

    __shared__ __nv_bfloat16 Ash[128 * 40];
    __shared__ __nv_bfloat16 Asl[128 * 40];
    __shared__ __nv_bfloat16 Bsh[32 * 136];
    __shared__ __nv_bfloat16 Bsl[32 * 136];

    int t = threadIdx.x;
    int lane = t & 31, wid = t >> 5;
    int wm = (wid >> 1) * 32;
    int wn = (wid & 1) * 64;

    float acc[2][8][4];
#pragma unroll
    for (int i = 0; i < 2; i++)
#pragma unroll
        for (int j = 0; j < 8; j++)
#pragma unroll
            for (int c = 0; c < 4; c++) acc[i][j][c] = 0.f;

    int am[2], ac[2], bk[2], bc[2];
    am[0] = t >> 2;        ac[0] = (t & 3) << 3;
    am[1] = (t >> 2) + 64; ac[1] = ac[0];
    bk[0] = t >> 4;        bc[0] = (t & 15) << 3;
    bk[1] = bk[0] + 16;    bc[1] = bc[0];

    uint4 rah[2], ral[2], rbh[2], rbl[2];
    const uint4 z4 = make_uint4(0u, 0u, 0u, 0u);

    uint32_t ash_b = s2u(Ash), asl_b = s2u(Asl);
    uint32_t bsh_b = s2u(Bsh), bsl_b = s2u(Bsl);

#define P_LOAD(K0) do { \
    _Pragma("unroll") \
    for (int s = 0; s < 2; s++) { \
        if (am[s] < 80) { \
            rah[s] = *(const uint4*)(Ah + (size_t)am[s] * LL + (K0) + ac[s]); \
            ral[s] = *(const uint4*)(Al + (size_t)am[s] * LL + (K0) + ac[s]); \
        } else { rah[s] = z4; ral[s] = z4; } \
        rbh[s] = *(const uint4*)(Bh + (size_t)((K0) + bk[s]) * HH + n0 + bc[s]); \
        rbl[s] = *(const uint4*)(Bl + (size_t)((K0) + bk[s]) * HH + n0 + bc[s]); \
    } } while (0)

#define P_STORE() do { \
    _Pragma("unroll") \
    for (int s = 0; s < 2; s++) { \
        *(uint4*)&Ash[am[s] * 40 + ac[s]] = rah[s]; \
        *(uint4*)&Asl[am[s] * 40 + ac[s]] = ral[s]; \
        *(uint4*)&Bsh[bk[s] * 136 + bc[s]] = rbh[s]; \
        *(uint4*)&Bsl[bk[s] * 136 + bc[s]] = rbl[s]; \
    } } while (0)

    P_LOAD(0);
    P_STORE();
    __syncthreads();

    for (int kt = 0; kt < 32; kt++) {
        if (kt + 1 < 32) P_LOAD((kt + 1) * 32);
#pragma unroll
        for (int ks = 0; ks < 2; ks++) {
            uint32_t ah[2][4], al[2][4], bh[8][2], bl[8][2];
            int ar  = lane & 15;
            int acf = ks * 16 + ((lane >> 4) << 3);
#pragma unroll
            for (int i = 0; i < 2; i++) {
                uint32_t off = (uint32_t)(((wm + i * 16 + ar) * 40 + acf) * 2);
                ldsm4(ash_b + off, ah[i]);
                ldsm4(asl_b + off, al[i]);
            }
            int br  = ks * 16 + (lane & 15);
            int bcf = (lane >> 4) << 3;
#pragma unroll
            for (int jj = 0; jj < 4; jj++) {
                uint32_t off = (uint32_t)((br * 136 + wn + jj * 16 + bcf) * 2);
                ldsm4t(bsh_b + off, bh[2 * jj], bh[2 * jj + 1]);
                ldsm4t(bsl_b + off, bl[2 * jj], bl[2 * jj + 1]);
            }
#pragma unroll
            for (int i = 0; i < 2; i++)
#pragma unroll
                for (int j = 0; j < 8; j++) {
                    MMA(acc[i][j], ah[i], bh[j]);
                    MMA(acc[i][j], ah[i], bl[j]);
                    MMA(acc[i][j], al[i], bh[j]);
                }
        }
        __syncthreads();
        if (kt + 1 < 32) { P_STORE(); __syncthreads(); }
    }

    // epilogue: split -> joint layout (b*40+q, s*1024 + h)
    int g = lane >> 2, tig = lane & 3;
#pragma unroll
    for (int i = 0; i < 2; i++)
#pragma unroll
        for (int j = 0; j < 8; j++) {
            int mb = wm + i * 16 + g;
            int n  = n0 + wn + j * 8 + tig * 2;
#pragma unroll
            for (int half = 0; half < 2; half++) {
                int m = mb + half * 8;
                if (m < 80) {
                    int jr  = b * QQ + (m >> 1);
                    int col = (m & 1) * HH + n;
                    __nv_bfloat16 h0, l0, h1, l1;
                    bsplit(acc[i][j][half * 2 + 0], h0, l0);
                    bsplit(acc[i][j][half * 2 + 1], h1, l1);
                    __nv_bfloat162 hv; hv.x = h0; hv.y = h1;
                    __nv_bfloat162 lv; lv.x = l0; lv.y = l1;
                    *(__nv_bfloat162*)&g_J_hi[(size_t)jr * 2048 + col] = hv;
                    *(__nv_bfloat162*)&g_J_lo[(size_t)jr * 2048 + col] = lv;
                }
            }
        }
#undef P_LOAD
#undef P_STORE
}

// ---------------- MLP0 GEMM (tensor): hidden(1280,1024)=relu(J(1280,2048)@w0(2048,1024)+ctrb) --------
// BM=64, BN=128, BK=32. 8 warps as 2x4; warp tile 32x32.
__global__ void __launch_bounds__(256, 1) k_mlp0_mma() {
    int m0 = blockIdx.y * 64;
    int n0 = blockIdx.x * 128;

    __shared__ __nv_bfloat16 Ash[64 * 40];
    __shared__ __nv_bfloat16 Asl[64 * 40];
    __shared__ __nv_bfloat16 Bsh[32 * 136];
    __shared__ __nv_bfloat16 Bsl[32 * 136];

    int t = threadIdx.x;
    int lane = t & 31, wid = t >> 5;
    int wm = (wid >> 2) * 32;
    int wn = (wid & 3) * 32;

    float acc[2][4][4];
#pragma unroll
    for (int i = 0; i < 2; i++)
#pragma unroll
        for (int j = 0; j < 4; j++)
#pragma unroll
            for (int c = 0; c < 4; c++) acc[i][j][c] = 0.f;

    int am = t >> 2, ac = (t & 3) << 3;
    int bk[2], bc;
    bk[0] = t >> 4; bk[1] = bk[0] + 16; bc = (t & 15) << 3;

    uint4 rah, ral, rbh[2], rbl[2];

    uint32_t ash_b = s2u(Ash), asl_b = s2u(Asl);
    uint32_t bsh_b = s2u(Bsh), bsl_b = s2u(Bsl);

#define M_LOAD(K0) do { \
    rah = *(const uint4*)(g_J_hi + (size_t)(m0 + am) * 2048 + (K0) + ac); \
    ral = *(const uint4*)(g_J_lo + (size_t)(m0 + am) * 2048 + (K0) + ac); \
    _Pragma("unroll") \
    for (int s = 0; s < 2; s++) { \
        rbh[s] = *(const uint4*)(g_w0_hi + (size_t)((K0) + bk[s]) * HH + n0 + bc); \
        rbl[s] = *(const uint4*)(g_w0_lo + (size_t)((K0) + bk[s]) * HH + n0 + bc); \
    } } while (0)

#define M_STORE() do { \
    *(uint4*)&Ash[am * 40 + ac] = rah; \
    *(uint4*)&Asl[am * 40 + ac] = ral; \
    _Pragma("unroll") \
    for (int s = 0; s < 2; s++) { \
        *(uint4*)&Bsh[bk[s] * 136 + bc] = rbh[s]; \
        *(uint4*)&Bsl[bk[s] * 136 + bc] = rbl[s]; \
    } } while (0)

    M_LOAD(0);
    M_STORE();
    __syncthreads();

    for (int kt = 0; kt < 64; kt++) {
        if (kt + 1 < 64) M_LOAD((kt + 1) * 32);
#pragma unroll
        for (int ks = 0; ks < 2; ks++) {
            uint32_t ah[2][4], al[2][4], bh[4][2], bl[4][2];
            int ar  = lane & 15;
            int acf = ks * 16 + ((lane >> 4) << 3);
#pragma unroll
            for (int i = 0; i < 2; i++) {
                uint32_t off = (uint32_t)(((wm + i * 16 + ar) * 40 + acf) * 2);
                ldsm4(ash_b + off, ah[i]);
                ldsm4(asl_b + off, al[i]);
            }
            int br  = ks * 16 + (lane & 15);
            int bcf = (lane >> 4) << 3;
#pragma unroll
            for (int jj = 0; jj < 2; jj++) {
                uint32_t off = (uint32_t)((br * 136 + wn + jj * 16 + bcf) * 2);
                ldsm4t(bsh_b + off, bh[2 * jj], bh[2 * jj + 1]);
                ldsm4t(bsl_b + off, bl[2 * jj], bl[2 * jj + 1]);
            }
#pragma unroll
            for (int i = 0; i < 2; i++)
#pragma unroll
                for (int j = 0; j < 4; j++) {
                    MMA(acc[i][j], ah[i], bh[j]);
                    MMA(acc[i][j], ah[i], bl[j]);
                    MMA(acc[i][j], al[i], bh[j]);
                }
        }
        __syncthreads();
        if (kt + 1 < 64) { M_STORE(); __syncthreads(); }
    }

    int g = lane >> 2, tig = lane & 3;
#pragma unroll
    for (int i = 0; i < 2; i++)
#pragma unroll
        for (int j = 0; j < 4; j++) {
            int n = n0 + wn + j * 8 + tig * 2;
#pragma unroll
            for (int half = 0; half < 2; half++) {
                int row = m0 + wm + i * 16 + g + half * 8;
                int bb = row / QQ;
                float v0 = fmaxf(acc[i][j][half * 2 + 0] + g_txtctrb[bb * HH + n], 0.f);
                float v1 = fmaxf(acc[i][j][half * 2 + 1] + g_txtctrb[bb * HH + n + 1], 0.f);
                float2 v; v.x = v0; v.y = v1;
                *(float2*)&g_hidden[(size_t)row * HH + n] = v;
            }
        }
#undef M_LOAD
#undef M_STORE
}

// ---------------- MLP1 + state update + output ----------------
__global__ void k_mlp1(const float* __restrict__ m1w, const float* __restrict__ m1b,
                       float* __restrict__ out, int pass, int last) {
    int r = blockIdx.x, t = threadIdx.x;
    const float* hrow = g_hidden + (size_t)r * HH;
    float a0 = 0.f, a1 = 0.f;
    for (int h = t; h < HH; h += 256) {
        float x = hrow[h];
        a0 += x * m1w[h * 2 + 0];
        a1 += x * m1w[h * 2 + 1];
    }
    __shared__ float s0[256], s1[256];
    s0[t] = a0; s1[t] = a1; __syncthreads();
    for (int ofs = 128; ofs > 0; ofs >>= 1) {
        if (t < ofs) { s0[t] += s0[t + ofs]; s1[t] += s1[t + ofs]; }
        __syncthreads();
    }
    if (t == 0) {
        float d0 = tanhf(s0[0] + m1b[0]) * MAX_DELTA_C;
        float d1 = tanhf(s1[0] + m1b[1]) * MAX_DELTA_C;
        float s = fminf(fmaxf(g_state[r * 2 + 0] + d0, 0.f), 1.f);
        float e = fminf(fmaxf(g_state[r * 2 + 1] + d1, 0.f), 1.f);
        g_state[r * 2 + 0] = s;
        g_state[r * 2 + 1] = e;
        float c = 0.5f * (s + e);
        float w = fmaxf(e - s, 1e-6f);
        int base = (1 + pass) * BB * QQ * 2;
        out[base + r * 2 + 0] = c;
        out[base + r * 2 + 1] = w;
        if (pass == last) {
            out[r * 2 + 0] = c;
            out[r * 2 + 1] = w;
        }
    }
}

extern "C" void kernel_launch(void* const* d_in, const int* in_sizes, int n_in,
                              void* d_out, int out_size) {
    const float* pred = (const float*)d_in[0];
    const float* vid  = (const float*)d_in[1];
    const float* mask = (const float*)d_in[2];
    const float* txt  = (const float*)d_in[3];
    const float* ls   = (const float*)d_in[4];
    const float* le   = (const float*)d_in[5];
    const float* sws  = (const float*)d_in[6];
    const float* swe  = (const float*)d_in[7];
    const float* tpw  = (const float*)d_in[8];
    const float* tpb  = (const float*)d_in[9];
    const float* m0w  = (const float*)d_in[10];
    const float* m0b  = (const float*)d_in[11];
    const float* m1w  = (const float*)d_in[12];
    const float* m1b  = (const float*)d_in[13];
    float* out = (float*)d_out;

    // one-time per launch: split constants to bf16 hi/lo
    k_cvt_vid<<<(BB * LL * HH / 4) / 256, 256>>>(vid);
    k_cvt_w0<<<(2 * HH * HH / 4) / 256, 256>>>(m0w);
    k_txt_off<<<BB, 256>>>(txt, tpw, tpb);
    k_txt_ctrb<<<dim3(HH / 256, BB), 256>>>(txt, m0w, m0b);
    k_init<<<(BB * QQ + 255) / 256, 256>>>(pred);

    for (int p = 0; p < 2; p++) {
        k_weights<<<BB * QQ, 256>>>(mask, ls, le, sws, swe);
        k_pool_mma<<<dim3(HH / 128, BB), 256>>>();
        k_mlp0_mma<<<dim3(HH / 128, (BB * QQ) / 64), 256>>>();
        k_mlp1<<<BB * QQ, 256>>>(m1w, m1b, out, p, 1);
    }
}

// round 3
// speedup vs baseline: 3.7470x; 1.5538x over previous
#include <cuda_runtime.h>
#include <cuda_bf16.h>
#include <math.h>
#include <stdint.h>

#define BB 32
#define QQ 40
#define LL 1024
#define HH 1024
#define MIN_SIG (1.0f/4096.0f)
#define HALF_LOG_RANGE 4.9999975e-07f
#define MAX_DELTA_C 0.1f

// -------- device scratch (static; no runtime allocation) --------
__device__ __nv_bfloat16 g_w0_hi[2 * HH * HH];
__device__ __nv_bfloat16 g_w0_lo[2 * HH * HH];
__device__ __nv_bfloat16 g_W_hi[BB * 80 * LL];
__device__ __nv_bfloat16 g_W_lo[BB * 80 * LL];
__device__ __nv_bfloat16 g_J_hi[BB * QQ * 2 * HH];   // joint (1280, 2048)
__device__ __nv_bfloat16 g_J_lo[BB * QQ * 2 * HH];
__device__ float g_hidden[BB * QQ * HH];
__device__ float g_state[BB * QQ * 2];
__device__ float g_txtoff[BB * 2];
__device__ float g_txtctrb[BB * HH];
__device__ float g_ctrb_part[4][BB * HH];

// ---------------- helpers ----------------
__device__ __forceinline__ void bsplit(float v, __nv_bfloat16& h, __nv_bfloat16& l) {
    h = __float2bfloat16(v);
    l = __float2bfloat16(v - __bfloat162float(h));
}
__device__ __forceinline__ uint32_t s2u(const void* p) {
    return (uint32_t)__cvta_generic_to_shared(p);
}
__device__ __forceinline__ void ldsm4(uint32_t addr, uint32_t* r) {
    asm volatile("ldmatrix.sync.aligned.m8n8.x4.shared.b16 {%0,%1,%2,%3}, [%4];"
        : "=r"(r[0]), "=r"(r[1]), "=r"(r[2]), "=r"(r[3]) : "r"(addr));
}
__device__ __forceinline__ void ldsm4t(uint32_t addr, uint32_t* r01, uint32_t* r23) {
    asm volatile("ldmatrix.sync.aligned.m8n8.x4.trans.shared.b16 {%0,%1,%2,%3}, [%4];"
        : "=r"(r01[0]), "=r"(r01[1]), "=r"(r23[0]), "=r"(r23[1]) : "r"(addr));
}
#define MMA(c, a, b) asm volatile( \
    "mma.sync.aligned.m16n8k16.row.col.f32.bf16.bf16.f32 " \
    "{%0,%1,%2,%3}, {%4,%5,%6,%7}, {%8,%9}, {%0,%1,%2,%3};\n" \
    : "+f"((c)[0]), "+f"((c)[1]), "+f"((c)[2]), "+f"((c)[3]) \
    : "r"((a)[0]), "r"((a)[1]), "r"((a)[2]), "r"((a)[3]), \
      "r"((b)[0]), "r"((b)[1]))

__device__ __forceinline__ uint32_t pack2(__nv_bfloat16 a, __nv_bfloat16 b) {
    __nv_bfloat162 v; v.x = a; v.y = b;
    return *(uint32_t*)&v;
}

// ---------------- w0 split (first 2H rows only) ----------------
__global__ void k_cvt_w0(const float* __restrict__ src) {
    int i = blockIdx.x * 256 + threadIdx.x;
    float4 v = ((const float4*)src)[i];
    __nv_bfloat16 h0, h1, h2, h3, l0, l1, l2, l3;
    bsplit(v.x, h0, l0); bsplit(v.y, h1, l1);
    bsplit(v.z, h2, l2); bsplit(v.w, h3, l3);
    ((uint2*)g_w0_hi)[i] = make_uint2(pack2(h0, h1), pack2(h2, h3));
    ((uint2*)g_w0_lo)[i] = make_uint2(pack2(l0, l1), pack2(l2, l3));
}

// ---------------- txt offset ----------------
__global__ void k_txt_off(const float* __restrict__ txt_rep,
                          const float* __restrict__ tpw,
                          const float* __restrict__ tpb) {
    int b = blockIdx.x, t = threadIdx.x;
    float a0 = 0.f, a1 = 0.f;
    for (int h = t; h < HH; h += 256) {
        float x = txt_rep[b * HH + h];
        a0 += x * tpw[h * 2 + 0];
        a1 += x * tpw[h * 2 + 1];
    }
    __shared__ float s0[256], s1[256];
    s0[t] = a0; s1[t] = a1; __syncthreads();
    for (int ofs = 128; ofs > 0; ofs >>= 1) {
        if (t < ofs) { s0[t] += s0[t + ofs]; s1[t] += s1[t + ofs]; }
        __syncthreads();
    }
    if (t == 0) {
        g_txtoff[b * 2 + 0] = tanhf(s0[0] + tpb[0]) * HALF_LOG_RANGE;
        g_txtoff[b * 2 + 1] = tanhf(s1[0] + tpb[1]) * HALF_LOG_RANGE;
    }
}

// ---------------- txt contribution to mlp0 (k-split x4, unroll 16) ----------------
__global__ void k_txt_ctrb(const float* __restrict__ txt_rep,
                           const float* __restrict__ m0w) {
    int b = blockIdx.y;
    int ks = blockIdx.z;
    int h = blockIdx.x * 256 + threadIdx.x;
    const float* wp = m0w + (size_t)2 * HH * HH + h;
    const float* xr = txt_rep + (size_t)b * HH;
    float acc = 0.f;
    int k0 = ks * 256;
#pragma unroll 16
    for (int k = k0; k < k0 + 256; k++) acc += xr[k] * wp[(size_t)k * HH];
    g_ctrb_part[ks][b * HH + h] = acc;
}

__global__ void k_ctrb_reduce(const float* __restrict__ m0b) {
    int i = blockIdx.x * 256 + threadIdx.x;     // over BB*HH
    int h = i & (HH - 1);
    g_txtctrb[i] = g_ctrb_part[0][i] + g_ctrb_part[1][i] +
                   g_ctrb_part[2][i] + g_ctrb_part[3][i] + m0b[h];
}

// ---------------- init start/end ----------------
__global__ void k_init(const float* __restrict__ pred) {
    int r = blockIdx.x * blockDim.x + threadIdx.x;
    if (r < BB * QQ) {
        float c = pred[r * 2 + 0], w = pred[r * 2 + 1];
        g_state[r * 2 + 0] = fminf(fmaxf(c - 0.5f * w, 0.f), 1.f);
        g_state[r * 2 + 1] = fminf(fmaxf(c + 0.5f * w, 0.f), 1.f);
    }
}

// ---------------- gaussian weights -> bf16 hi/lo ----------------
__global__ void k_weights(const float* __restrict__ vid_mask,
                          const float* __restrict__ ls_p, const float* __restrict__ le_p,
                          const float* __restrict__ sws_p, const float* __restrict__ swe_p) {
    int r = blockIdx.x;        // b*Q + q
    int b = r / QQ;
    int t = threadIdx.x;
    float s = g_state[r * 2 + 0], e = g_state[r * 2 + 1];
    float width = fmaxf(e - s, 1e-6f);
    float sig_s = fmaxf(expf(ls_p[0] + sws_p[0] * width + g_txtoff[b * 2 + 0]), MIN_SIG);
    float sig_e = fmaxf(expf(le_p[0] + swe_p[0] * width + g_txtoff[b * 2 + 1]), MIN_SIG);
    float inv_ss = 1.0f / sig_s, inv_se = 1.0f / sig_e;

    const float* mrow = vid_mask + (size_t)b * LL;
    float ws[4], we[4];
    float sum_s = 0.f, sum_e = 0.f;
#pragma unroll
    for (int i = 0; i < 4; i++) {
        int l = t + i * 256;
        float tp = (float)l * (1.0f / 1023.0f);
        float m = mrow[l];
        float ds = (tp - s) * inv_ss;
        float vs = expf(-0.5f * ds * ds) * m;
        float de = (tp - e) * inv_se;
        float ve = expf(-0.5f * de * de) * m;
        ws[i] = vs; we[i] = ve;
        sum_s += vs; sum_e += ve;
    }
    __shared__ float r0[256], r1[256];
    r0[t] = sum_s; r1[t] = sum_e; __syncthreads();
    for (int ofs = 128; ofs > 0; ofs >>= 1) {
        if (t < ofs) { r0[t] += r0[t + ofs]; r1[t] += r1[t + ofs]; }
        __syncthreads();
    }
    float is = 1.0f / fmaxf(r0[0], 1e-8f);
    float ie = 1.0f / fmaxf(r1[0], 1e-8f);
    size_t rs = (size_t)(r * 2 + 0) * LL;
    size_t re = (size_t)(r * 2 + 1) * LL;
#pragma unroll
    for (int i = 0; i < 4; i++) {
        int l = t + i * 256;
        __nv_bfloat16 h, lo;
        bsplit(ws[i] * is, h, lo);
        g_W_hi[rs + l] = h; g_W_lo[rs + l] = lo;
        bsplit(we[i] * ie, h, lo);
        g_W_hi[re + l] = h; g_W_lo[re + l] = lo;
    }
}

// ---------------- pool GEMM: per batch C(80,1024)=W(80,1024)@V(1024,1024) ----------------
// BM=80 exact, BN=128, BK=32. 8 warps 1x8 (each warp: all 80 rows x 16 cols).
// vid read as fp32 and split to bf16 hi/lo while staging into smem.
__global__ void __launch_bounds__(256, 1) k_pool_mma(const float* __restrict__ vid) {
    int b  = blockIdx.y;
    int n0 = blockIdx.x * 128;
    const __nv_bfloat16* Ah = g_W_hi + (size_t)b * 80 * LL;
    const __nv_bfloat16* Al = g_W_lo + (size_t)b * 80 * LL;
    const float* Bv = vid + (size_t)b * LL * HH;

    __shared__ __nv_bfloat16 Ash[80 * 40];
    __shared__ __nv_bfloat16 Asl[80 * 40];
    __shared__ __nv_bfloat16 Bsh[32 * 136];
    __shared__ __nv_bfloat16 Bsl[32 * 136];

    int t = threadIdx.x;
    int lane = t & 31, wid = t >> 5;
    int wn = wid * 16;

    float acc[5][2][4];
#pragma unroll
    for (int i = 0; i < 5; i++)
#pragma unroll
        for (int j = 0; j < 2; j++)
#pragma unroll
            for (int c = 0; c < 4; c++) acc[i][j][c] = 0.f;

    // A: 320 uint4 loads (80 rows x 4 col-groups of 8)
    int ar0 = t >> 2,          ac0 = (t & 3) << 3;
    int ar1 = (t + 256) >> 2,  ac1 = ac0;
    bool a1v = (t < 64);
    // B: 1024 float4 loads, 4 per thread
    uint4 rah0, ral0, rah1, ral1;
    float4 rb[4];

    uint32_t ash_b = s2u(Ash), asl_b = s2u(Asl);
    uint32_t bsh_b = s2u(Bsh), bsl_b = s2u(Bsl);

#define P_LOAD(K0) do { \
    rah0 = *(const uint4*)(Ah + (size_t)ar0 * LL + (K0) + ac0); \
    ral0 = *(const uint4*)(Al + (size_t)ar0 * LL + (K0) + ac0); \
    if (a1v) { \
        rah1 = *(const uint4*)(Ah + (size_t)ar1 * LL + (K0) + ac1); \
        ral1 = *(const uint4*)(Al + (size_t)ar1 * LL + (K0) + ac1); \
    } \
    _Pragma("unroll") \
    for (int s = 0; s < 4; s++) { \
        int idx = t + s * 256; \
        int k = idx >> 5, c4 = idx & 31; \
        rb[s] = *(const float4*)(Bv + (size_t)((K0) + k) * HH + n0 + c4 * 4); \
    } } while (0)

#define P_STORE() do { \
    *(uint4*)&Ash[ar0 * 40 + ac0] = rah0; \
    *(uint4*)&Asl[ar0 * 40 + ac0] = ral0; \
    if (a1v) { \
        *(uint4*)&Ash[ar1 * 40 + ac1] = rah1; \
        *(uint4*)&Asl[ar1 * 40 + ac1] = ral1; \
    } \
    _Pragma("unroll") \
    for (int s = 0; s < 4; s++) { \
        int idx = t + s * 256; \
        int k = idx >> 5, c4 = idx & 31; \
        __nv_bfloat16 h0, h1, h2, h3, l0, l1, l2, l3; \
        bsplit(rb[s].x, h0, l0); bsplit(rb[s].y, h1, l1); \
        bsplit(rb[s].z, h2, l2); bsplit(rb[s].w, h3, l3); \
        *(uint2*)&Bsh[k * 136 + c4 * 4] = make_uint2(pack2(h0, h1), pack2(h2, h3)); \
        *(uint2*)&Bsl[k * 136 + c4 * 4] = make_uint2(pack2(l0, l1), pack2(l2, l3)); \
    } } while (0)

    P_LOAD(0);
    P_STORE();
    __syncthreads();

    for (int kt = 0; kt < 32; kt++) {
        if (kt + 1 < 32) P_LOAD((kt + 1) * 32);
#pragma unroll
        for (int ks = 0; ks < 2; ks++) {
            uint32_t ah[5][4], al[5][4], bh[2][2], bl[2][2];
            int ar  = lane & 15;
            int acf = ks * 16 + ((lane >> 4) << 3);
#pragma unroll
            for (int i = 0; i < 5; i++) {
                uint32_t off = (uint32_t)(((i * 16 + ar) * 40 + acf) * 2);
                ldsm4(ash_b + off, ah[i]);
                ldsm4(asl_b + off, al[i]);
            }
            int br  = ks * 16 + (lane & 15);
            int bcf = (lane >> 4) << 3;
            uint32_t boff = (uint32_t)((br * 136 + wn + bcf) * 2);
            ldsm4t(bsh_b + boff, bh[0], bh[1]);
            ldsm4t(bsl_b + boff, bl[0], bl[1]);
#pragma unroll
            for (int i = 0; i < 5; i++)
#pragma unroll
                for (int j = 0; j < 2; j++) {
                    MMA(acc[i][j], ah[i], bh[j]);
                    MMA(acc[i][j], ah[i], bl[j]);
                    MMA(acc[i][j], al[i], bh[j]);
                }
        }
        __syncthreads();
        if (kt + 1 < 32) { P_STORE(); __syncthreads(); }
    }

    // epilogue: split -> joint layout row b*40+q, col s*1024 + h
    int g = lane >> 2, tig = lane & 3;
#pragma unroll
    for (int i = 0; i < 5; i++)
#pragma unroll
        for (int j = 0; j < 2; j++) {
            int n = n0 + wn + j * 8 + tig * 2;
#pragma unroll
            for (int half = 0; half < 2; half++) {
                int m = i * 16 + g + half * 8;
                int jr  = b * QQ + (m >> 1);
                int col = (m & 1) * HH + n;
                __nv_bfloat16 h0, l0, h1, l1;
                bsplit(acc[i][j][half * 2 + 0], h0, l0);
                bsplit(acc[i][j][half * 2 + 1], h1, l1);
                *(uint32_t*)&g_J_hi[(size_t)jr * 2048 + col] = pack2(h0, h1);
                *(uint32_t*)&g_J_lo[(size_t)jr * 2048 + col] = pack2(l0, l1);
            }
        }
#undef P_LOAD
#undef P_STORE
}

// ---------------- MLP0 GEMM: hidden(1280,1024)=relu(J(1280,2048)@w0 + txtctrb) ----------------
// BM=80, BN=128, BK=32, grid 8x16 = 128 blocks (one wave). 8 warps 1x8.
__global__ void __launch_bounds__(256, 1) k_mlp0_mma() {
    int m0 = blockIdx.y * 80;
    int n0 = blockIdx.x * 128;

    __shared__ __nv_bfloat16 Ash[80 * 40];
    __shared__ __nv_bfloat16 Asl[80 * 40];
    __shared__ __nv_bfloat16 Bsh[32 * 136];
    __shared__ __nv_bfloat16 Bsl[32 * 136];

    int t = threadIdx.x;
    int lane = t & 31, wid = t >> 5;
    int wn = wid * 16;

    float acc[5][2][4];
#pragma unroll
    for (int i = 0; i < 5; i++)
#pragma unroll
        for (int j = 0; j < 2; j++)
#pragma unroll
            for (int c = 0; c < 4; c++) acc[i][j][c] = 0.f;

    int ar0 = t >> 2,          ac0 = (t & 3) << 3;
    int ar1 = (t + 256) >> 2,  ac1 = ac0;
    bool a1v = (t < 64);
    // B: 32x128 bf16 = 512 uint4, 2 per thread
    uint4 rah0, ral0, rah1, ral1, rbh[2], rbl[2];

    uint32_t ash_b = s2u(Ash), asl_b = s2u(Asl);
    uint32_t bsh_b = s2u(Bsh), bsl_b = s2u(Bsl);

#define M_LOAD(K0) do { \
    rah0 = *(const uint4*)(g_J_hi + (size_t)(m0 + ar0) * 2048 + (K0) + ac0); \
    ral0 = *(const uint4*)(g_J_lo + (size_t)(m0 + ar0) * 2048 + (K0) + ac0); \
    if (a1v) { \
        rah1 = *(const uint4*)(g_J_hi + (size_t)(m0 + ar1) * 2048 + (K0) + ac1); \
        ral1 = *(const uint4*)(g_J_lo + (size_t)(m0 + ar1) * 2048 + (K0) + ac1); \
    } \
    _Pragma("unroll") \
    for (int s = 0; s < 2; s++) { \
        int idx = t + s * 256; \
        int k = idx >> 4, c8 = (idx & 15) << 3; \
        rbh[s] = *(const uint4*)(g_w0_hi + (size_t)((K0) + k) * HH + n0 + c8); \
        rbl[s] = *(const uint4*)(g_w0_lo + (size_t)((K0) + k) * HH + n0 + c8); \
    } } while (0)

#define M_STORE() do { \
    *(uint4*)&Ash[ar0 * 40 + ac0] = rah0; \
    *(uint4*)&Asl[ar0 * 40 + ac0] = ral0; \
    if (a1v) { \
        *(uint4*)&Ash[ar1 * 40 + ac1] = rah1; \
        *(uint4*)&Asl[ar1 * 40 + ac1] = ral1; \
    } \
    _Pragma("unroll") \
    for (int s = 0; s < 2; s++) { \
        int idx = t + s * 256; \
        int k = idx >> 4, c8 = (idx & 15) << 3; \
        *(uint4*)&Bsh[k * 136 + c8] = rbh[s]; \
        *(uint4*)&Bsl[k * 136 + c8] = rbl[s]; \
    } } while (0)

    M_LOAD(0);
    M_STORE();
    __syncthreads();

    for (int kt = 0; kt < 64; kt++) {
        if (kt + 1 < 64) M_LOAD((kt + 1) * 32);
#pragma unroll
        for (int ks = 0; ks < 2; ks++) {
            uint32_t ah[5][4], al[5][4], bh[2][2], bl[2][2];
            int ar  = lane & 15;
            int acf = ks * 16 + ((lane >> 4) << 3);
#pragma unroll
            for (int i = 0; i < 5; i++) {
                uint32_t off = (uint32_t)(((i * 16 + ar) * 40 + acf) * 2);
                ldsm4(ash_b + off, ah[i]);
                ldsm4(asl_b + off, al[i]);
            }
            int br  = ks * 16 + (lane & 15);
            int bcf = (lane >> 4) << 3;
            uint32_t boff = (uint32_t)((br * 136 + wn + bcf) * 2);
            ldsm4t(bsh_b + boff, bh[0], bh[1]);
            ldsm4t(bsl_b + boff, bl[0], bl[1]);
#pragma unroll
            for (int i = 0; i < 5; i++)
#pragma unroll
                for (int j = 0; j < 2; j++) {
                    MMA(acc[i][j], ah[i], bh[j]);
                    MMA(acc[i][j], ah[i], bl[j]);
                    MMA(acc[i][j], al[i], bh[j]);
                }
        }
        __syncthreads();
        if (kt + 1 < 64) { M_STORE(); __syncthreads(); }
    }

    int g = lane >> 2, tig = lane & 3;
#pragma unroll
    for (int i = 0; i < 5; i++)
#pragma unroll
        for (int j = 0; j < 2; j++) {
            int n = n0 + wn + j * 8 + tig * 2;
#pragma unroll
            for (int half = 0; half < 2; half++) {
                int row = m0 + i * 16 + g + half * 8;
                int bb = row / QQ;
                float v0 = fmaxf(acc[i][j][half * 2 + 0] + g_txtctrb[bb * HH + n], 0.f);
                float v1 = fmaxf(acc[i][j][half * 2 + 1] + g_txtctrb[bb * HH + n + 1], 0.f);
                float2 v; v.x = v0; v.y = v1;
                *(float2*)&g_hidden[(size_t)row * HH + n] = v;
            }
        }
#undef M_LOAD
#undef M_STORE
}

// ---------------- MLP1 + state update + output ----------------
__global__ void k_mlp1(const float* __restrict__ m1w, const float* __restrict__ m1b,
                       float* __restrict__ out, int pass, int last) {
    int r = blockIdx.x, t = threadIdx.x;
    const float* hrow = g_hidden + (size_t)r * HH;
    float a0 = 0.f, a1 = 0.f;
    for (int h = t; h < HH; h += 256) {
        float x = hrow[h];
        a0 += x * m1w[h * 2 + 0];
        a1 += x * m1w[h * 2 + 1];
    }
    __shared__ float s0[256], s1[256];
    s0[t] = a0; s1[t] = a1; __syncthreads();
    for (int ofs = 128; ofs > 0; ofs >>= 1) {
        if (t < ofs) { s0[t] += s0[t + ofs]; s1[t] += s1[t + ofs]; }
        __syncthreads();
    }
    if (t == 0) {
        float d0 = tanhf(s0[0] + m1b[0]) * MAX_DELTA_C;
        float d1 = tanhf(s1[0] + m1b[1]) * MAX_DELTA_C;
        float s = fminf(fmaxf(g_state[r * 2 + 0] + d0, 0.f), 1.f);
        float e = fminf(fmaxf(g_state[r * 2 + 1] + d1, 0.f), 1.f);
        g_state[r * 2 + 0] = s;
        g_state[r * 2 + 1] = e;
        float c = 0.5f * (s + e);
        float w = fmaxf(e - s, 1e-6f);
        int base = (1 + pass) * BB * QQ * 2;
        out[base + r * 2 + 0] = c;
        out[base + r * 2 + 1] = w;
        if (pass == last) {
            out[r * 2 + 0] = c;
            out[r * 2 + 1] = w;
        }
    }
}

extern "C" void kernel_launch(void* const* d_in, const int* in_sizes, int n_in,
                              void* d_out, int out_size) {
    const float* pred = (const float*)d_in[0];
    const float* vid  = (const float*)d_in[1];
    const float* mask = (const float*)d_in[2];
    const float* txt  = (const float*)d_in[3];
    const float* ls   = (const float*)d_in[4];
    const float* le   = (const float*)d_in[5];
    const float* sws  = (const float*)d_in[6];
    const float* swe  = (const float*)d_in[7];
    const float* tpw  = (const float*)d_in[8];
    const float* tpb  = (const float*)d_in[9];
    const float* m0w  = (const float*)d_in[10];
    const float* m0b  = (const float*)d_in[11];
    const float* m1w  = (const float*)d_in[12];
    const float* m1b  = (const float*)d_in[13];
    float* out = (float*)d_out;

    k_cvt_w0<<<(2 * HH * HH / 4) / 256, 256>>>(m0w);
    k_txt_off<<<BB, 256>>>(txt, tpw, tpb);
    k_txt_ctrb<<<dim3(HH / 256, BB, 4), 256>>>(txt, m0w);
    k_ctrb_reduce<<<(BB * HH) / 256, 256>>>(m0b);
    k_init<<<(BB * QQ + 255) / 256, 256>>>(pred);

    for (int p = 0; p < 2; p++) {
        k_weights<<<BB * QQ, 256>>>(mask, ls, le, sws, swe);
        k_pool_mma<<<dim3(HH / 128, BB), 256>>>(vid);
        k_mlp0_mma<<<dim3(HH / 128, (BB * QQ) / 80), 256>>>();
        k_mlp1<<<BB * QQ, 256>>>(m1w, m1b, out, p, 1);
    }
}

// round 4
// speedup vs baseline: 4.0374x; 1.0775x over previous
#include <cuda_runtime.h>
#include <cuda_bf16.h>
#include <math.h>
#include <stdint.h>

#define BB 32
#define QQ 40
#define LL 1024
#define HH 1024
#define MIN_SIG (1.0f/4096.0f)
#define HALF_LOG_RANGE 4.9999975e-07f
#define MAX_DELTA_C 0.1f

// smem tile layout (bf16 elems / bytes), per stage:
//   Ash 80*40  @ 0       (bytes 0)
//   Asl 80*40  @ 3200    (bytes 6400)
//   Bsh 32*136 @ 6400    (bytes 12800)
//   Bsl 32*136 @ 10752   (bytes 21504)
// stage stride = 15104 elems = 30208 bytes
#define ASLb 6400
#define BSHb 12800
#define BSLb 21504
#define STGb 30208
#define POOL_SMEM (2 * STGb)
#define MLP0_SMEM (3 * STGb)

// -------- device scratch --------
__device__ __nv_bfloat16 g_w0_hi[2 * HH * HH];
__device__ __nv_bfloat16 g_w0_lo[2 * HH * HH];
__device__ __nv_bfloat16 g_W_hi[BB * 80 * LL];
__device__ __nv_bfloat16 g_W_lo[BB * 80 * LL];
__device__ __nv_bfloat16 g_J_hi[BB * QQ * 2 * HH];
__device__ __nv_bfloat16 g_J_lo[BB * QQ * 2 * HH];
__device__ float g_hidden[BB * QQ * HH];
__device__ float g_state[BB * QQ * 2];
__device__ float g_txtoff[BB * 2];
__device__ float g_txtctrb[BB * HH];
__device__ float g_ctrb_part[4][BB * HH];

// ---------------- helpers ----------------
__device__ __forceinline__ void bsplit(float v, __nv_bfloat16& h, __nv_bfloat16& l) {
    h = __float2bfloat16(v);
    l = __float2bfloat16(v - __bfloat162float(h));
}
__device__ __forceinline__ uint32_t s2u(const void* p) {
    return (uint32_t)__cvta_generic_to_shared(p);
}
__device__ __forceinline__ void ldsm4(uint32_t addr, uint32_t* r) {
    asm volatile("ldmatrix.sync.aligned.m8n8.x4.shared.b16 {%0,%1,%2,%3}, [%4];"
        : "=r"(r[0]), "=r"(r[1]), "=r"(r[2]), "=r"(r[3]) : "r"(addr));
}
__device__ __forceinline__ void ldsm4t(uint32_t addr, uint32_t* r01, uint32_t* r23) {
    asm volatile("ldmatrix.sync.aligned.m8n8.x4.trans.shared.b16 {%0,%1,%2,%3}, [%4];"
        : "=r"(r01[0]), "=r"(r01[1]), "=r"(r23[0]), "=r"(r23[1]) : "r"(addr));
}
__device__ __forceinline__ void cpa16(uint32_t d, const void* g) {
    asm volatile("cp.async.cg.shared.global [%0], [%1], 16;" :: "r"(d), "l"(g));
}
#define CP_COMMIT() asm volatile("cp.async.commit_group;")
#define CP_WAIT(N)  asm volatile("cp.async.wait_group %0;" :: "n"(N))

#define MMA(c, a, b) asm volatile( \
    "mma.sync.aligned.m16n8k16.row.col.f32.bf16.bf16.f32 " \
    "{%0,%1,%2,%3}, {%4,%5,%6,%7}, {%8,%9}, {%0,%1,%2,%3};\n" \
    : "+f"((c)[0]), "+f"((c)[1]), "+f"((c)[2]), "+f"((c)[3]) \
    : "r"((a)[0]), "r"((a)[1]), "r"((a)[2]), "r"((a)[3]), \
      "r"((b)[0]), "r"((b)[1]))

__device__ __forceinline__ uint32_t pack2(__nv_bfloat16 a, __nv_bfloat16 b) {
    __nv_bfloat162 v; v.x = a; v.y = b;
    return *(uint32_t*)&v;
}

// ---------------- w0 split ----------------
__global__ void k_cvt_w0(const float* __restrict__ src) {
    int i = blockIdx.x * 256 + threadIdx.x;
    float4 v = ((const float4*)src)[i];
    __nv_bfloat16 h0, h1, h2, h3, l0, l1, l2, l3;
    bsplit(v.x, h0, l0); bsplit(v.y, h1, l1);
    bsplit(v.z, h2, l2); bsplit(v.w, h3, l3);
    ((uint2*)g_w0_hi)[i] = make_uint2(pack2(h0, h1), pack2(h2, h3));
    ((uint2*)g_w0_lo)[i] = make_uint2(pack2(l0, l1), pack2(l2, l3));
}

// ---------------- txt offset ----------------
__global__ void k_txt_off(const float* __restrict__ txt_rep,
                          const float* __restrict__ tpw,
                          const float* __restrict__ tpb) {
    int b = blockIdx.x, t = threadIdx.x;
    float a0 = 0.f, a1 = 0.f;
    for (int h = t; h < HH; h += 256) {
        float x = txt_rep[b * HH + h];
        a0 += x * tpw[h * 2 + 0];
        a1 += x * tpw[h * 2 + 1];
    }
    __shared__ float s0[256], s1[256];
    s0[t] = a0; s1[t] = a1; __syncthreads();
    for (int ofs = 128; ofs > 0; ofs >>= 1) {
        if (t < ofs) { s0[t] += s0[t + ofs]; s1[t] += s1[t + ofs]; }
        __syncthreads();
    }
    if (t == 0) {
        g_txtoff[b * 2 + 0] = tanhf(s0[0] + tpb[0]) * HALF_LOG_RANGE;
        g_txtoff[b * 2 + 1] = tanhf(s1[0] + tpb[1]) * HALF_LOG_RANGE;
    }
}

// ---------------- txt contribution to mlp0 (k-split x4) ----------------
__global__ void k_txt_ctrb(const float* __restrict__ txt_rep,
                           const float* __restrict__ m0w) {
    int b = blockIdx.y;
    int ks = blockIdx.z;
    int h = blockIdx.x * 256 + threadIdx.x;
    const float* wp = m0w + (size_t)2 * HH * HH + h;
    const float* xr = txt_rep + (size_t)b * HH;
    float acc = 0.f;
    int k0 = ks * 256;
#pragma unroll 16
    for (int k = k0; k < k0 + 256; k++) acc += xr[k] * wp[(size_t)k * HH];
    g_ctrb_part[ks][b * HH + h] = acc;
}

__global__ void k_ctrb_reduce(const float* __restrict__ m0b) {
    int i = blockIdx.x * 256 + threadIdx.x;
    int h = i & (HH - 1);
    g_txtctrb[i] = g_ctrb_part[0][i] + g_ctrb_part[1][i] +
                   g_ctrb_part[2][i] + g_ctrb_part[3][i] + m0b[h];
}

// ---------------- init ----------------
__global__ void k_init(const float* __restrict__ pred) {
    int r = blockIdx.x * blockDim.x + threadIdx.x;
    if (r < BB * QQ) {
        float c = pred[r * 2 + 0], w = pred[r * 2 + 1];
        g_state[r * 2 + 0] = fminf(fmaxf(c - 0.5f * w, 0.f), 1.f);
        g_state[r * 2 + 1] = fminf(fmaxf(c + 0.5f * w, 0.f), 1.f);
    }
}

// ---------------- gaussian weights -> bf16 hi/lo ----------------
__global__ void k_weights(const float* __restrict__ vid_mask,
                          const float* __restrict__ ls_p, const float* __restrict__ le_p,
                          const float* __restrict__ sws_p, const float* __restrict__ swe_p) {
    int r = blockIdx.x;
    int b = r / QQ;
    int t = threadIdx.x;
    float s = g_state[r * 2 + 0], e = g_state[r * 2 + 1];
    float width = fmaxf(e - s, 1e-6f);
    float sig_s = fmaxf(expf(ls_p[0] + sws_p[0] * width + g_txtoff[b * 2 + 0]), MIN_SIG);
    float sig_e = fmaxf(expf(le_p[0] + swe_p[0] * width + g_txtoff[b * 2 + 1]), MIN_SIG);
    float inv_ss = 1.0f / sig_s, inv_se = 1.0f / sig_e;

    const float* mrow = vid_mask + (size_t)b * LL;
    float ws[4], we[4];
    float sum_s = 0.f, sum_e = 0.f;
#pragma unroll
    for (int i = 0; i < 4; i++) {
        int l = t + i * 256;
        float tp = (float)l * (1.0f / 1023.0f);
        float m = mrow[l];
        float ds = (tp - s) * inv_ss;
        float vs = expf(-0.5f * ds * ds) * m;
        float de = (tp - e) * inv_se;
        float ve = expf(-0.5f * de * de) * m;
        ws[i] = vs; we[i] = ve;
        sum_s += vs; sum_e += ve;
    }
    __shared__ float r0[256], r1[256];
    r0[t] = sum_s; r1[t] = sum_e; __syncthreads();
    for (int ofs = 128; ofs > 0; ofs >>= 1) {
        if (t < ofs) { r0[t] += r0[t + ofs]; r1[t] += r1[t + ofs]; }
        __syncthreads();
    }
    float is = 1.0f / fmaxf(r0[0], 1e-8f);
    float ie = 1.0f / fmaxf(r1[0], 1e-8f);
    size_t rs = (size_t)(r * 2 + 0) * LL;
    size_t re = (size_t)(r * 2 + 1) * LL;
#pragma unroll
    for (int i = 0; i < 4; i++) {
        int l = t + i * 256;
        __nv_bfloat16 h, lo;
        bsplit(ws[i] * is, h, lo);
        g_W_hi[rs + l] = h; g_W_lo[rs + l] = lo;
        bsplit(we[i] * ie, h, lo);
        g_W_hi[re + l] = h; g_W_lo[re + l] = lo;
    }
}

// ---------------- pool GEMM: C(80,1024)=W(80,1024)@V(1024,1024) per batch ----------------
// BM=80, BN=128, BK=32. Register-staged DOUBLE-buffered smem, one sync/tile.
__global__ void __launch_bounds__(256) k_pool_mma(const float* __restrict__ vid) {
    extern __shared__ __nv_bfloat16 dsm[];
    int b  = blockIdx.y;
    int n0 = blockIdx.x * 128;
    const __nv_bfloat16* Ah = g_W_hi + (size_t)b * 80 * LL;
    const __nv_bfloat16* Al = g_W_lo + (size_t)b * 80 * LL;
    const float* Bv = vid + (size_t)b * LL * HH;

    int t = threadIdx.x;
    int lane = t & 31, wid = t >> 5;
    int wn = wid * 16;
    uint32_t sb = s2u(dsm);

    float acc[5][2][4];
#pragma unroll
    for (int i = 0; i < 5; i++)
#pragma unroll
        for (int j = 0; j < 2; j++)
#pragma unroll
            for (int c = 0; c < 4; c++) acc[i][j][c] = 0.f;

    int ar0 = t >> 2,         ac0 = (t & 3) << 3;
    int ar1 = (t + 256) >> 2, ac1 = ac0;
    bool a1v = (t < 64);
    uint4 rah0, ral0, rah1, ral1;
    float4 rb[4];

#define P_LOAD(K0) do { \
    rah0 = *(const uint4*)(Ah + (size_t)ar0 * LL + (K0) + ac0); \
    ral0 = *(const uint4*)(Al + (size_t)ar0 * LL + (K0) + ac0); \
    if (a1v) { \
        rah1 = *(const uint4*)(Ah + (size_t)ar1 * LL + (K0) + ac1); \
        ral1 = *(const uint4*)(Al + (size_t)ar1 * LL + (K0) + ac1); \
    } \
    _Pragma("unroll") \
    for (int s = 0; s < 4; s++) { \
        int idx = t + s * 256; \
        int k = idx >> 5, c4 = idx & 31; \
        rb[s] = *(const float4*)(Bv + (size_t)((K0) + k) * HH + n0 + c4 * 4); \
    } } while (0)

#define P_STORE(BUF) do { \
    __nv_bfloat16* base = dsm + (BUF) * (STGb / 2); \
    *(uint4*)&base[ar0 * 40 + ac0] = rah0; \
    *(uint4*)&base[ASLb / 2 + ar0 * 40 + ac0] = ral0; \
    if (a1v) { \
        *(uint4*)&base[ar1 * 40 + ac1] = rah1; \
        *(uint4*)&base[ASLb / 2 + ar1 * 40 + ac1] = ral1; \
    } \
    _Pragma("unroll") \
    for (int s = 0; s < 4; s++) { \
        int idx = t + s * 256; \
        int k = idx >> 5, c4 = idx & 31; \
        __nv_bfloat16 h0, h1, h2, h3, l0, l1, l2, l3; \
        bsplit(rb[s].x, h0, l0); bsplit(rb[s].y, h1, l1); \
        bsplit(rb[s].z, h2, l2); bsplit(rb[s].w, h3, l3); \
        *(uint2*)&base[BSHb / 2 + k * 136 + c4 * 4] = make_uint2(pack2(h0, h1), pack2(h2, h3)); \
        *(uint2*)&base[BSLb / 2 + k * 136 + c4 * 4] = make_uint2(pack2(l0, l1), pack2(l2, l3)); \
    } } while (0)

#define P_COMPUTE(BUF) do { \
    uint32_t ab = sb + (BUF) * STGb; \
    _Pragma("unroll") \
    for (int ks = 0; ks < 2; ks++) { \
        uint32_t ah[5][4], al[5][4], bh[2][2], bl[2][2]; \
        int ar  = lane & 15; \
        int acf = ks * 16 + ((lane >> 4) << 3); \
        _Pragma("unroll") \
        for (int i = 0; i < 5; i++) { \
            uint32_t off = (uint32_t)(((i * 16 + ar) * 40 + acf) * 2); \
            ldsm4(ab + off, ah[i]); \
            ldsm4(ab + ASLb + off, al[i]); \
        } \
        int br  = ks * 16 + (lane & 15); \
        int bcf = (lane >> 4) << 3; \
        uint32_t boff = (uint32_t)((br * 136 + wn + bcf) * 2); \
        ldsm4t(ab + BSHb + boff, bh[0], bh[1]); \
        ldsm4t(ab + BSLb + boff, bl[0], bl[1]); \
        _Pragma("unroll") \
        for (int i = 0; i < 5; i++) \
            _Pragma("unroll") \
            for (int j = 0; j < 2; j++) { \
                MMA(acc[i][j], ah[i], bh[j]); \
                MMA(acc[i][j], ah[i], bl[j]); \
                MMA(acc[i][j], al[i], bh[j]); \
            } \
    } } while (0)

    P_LOAD(0);
    P_STORE(0);
    __syncthreads();

    for (int kt = 0; kt < 32; kt++) {
        if (kt + 1 < 32) P_LOAD((kt + 1) * 32);
        P_COMPUTE(kt & 1);
        if (kt + 1 < 32) { P_STORE((kt + 1) & 1); __syncthreads(); }
    }

    int g = lane >> 2, tig = lane & 3;
#pragma unroll
    for (int i = 0; i < 5; i++)
#pragma unroll
        for (int j = 0; j < 2; j++) {
            int n = n0 + wn + j * 8 + tig * 2;
#pragma unroll
            for (int half = 0; half < 2; half++) {
                int m = i * 16 + g + half * 8;
                int jr  = b * QQ + (m >> 1);
                int col = (m & 1) * HH + n;
                __nv_bfloat16 h0, l0, h1, l1;
                bsplit(acc[i][j][half * 2 + 0], h0, l0);
                bsplit(acc[i][j][half * 2 + 1], h1, l1);
                *(uint32_t*)&g_J_hi[(size_t)jr * 2048 + col] = pack2(h0, h1);
                *(uint32_t*)&g_J_lo[(size_t)jr * 2048 + col] = pack2(l0, l1);
            }
        }
#undef P_LOAD
#undef P_STORE
#undef P_COMPUTE
}

// ---------------- MLP0 GEMM: hidden(1280,1024)=relu(J@w0 + ctrb) ----------------
// BM=80, BN=128, BK=32, 64 K-tiles, cp.async 3-stage pipeline.
__global__ void __launch_bounds__(256) k_mlp0_mma() {
    extern __shared__ __nv_bfloat16 dsm[];
    int m0 = blockIdx.y * 80;
    int n0 = blockIdx.x * 128;

    int t = threadIdx.x;
    int lane = t & 31, wid = t >> 5;
    int wn = wid * 16;
    uint32_t sb = s2u(dsm);

    float acc[5][2][4];
#pragma unroll
    for (int i = 0; i < 5; i++)
#pragma unroll
        for (int j = 0; j < 2; j++)
#pragma unroll
            for (int c = 0; c < 4; c++) acc[i][j][c] = 0.f;

#define M_PREFETCH(TILE, STG) do { \
    uint32_t s = sb + (STG) * STGb; \
    int k0 = (TILE) * 32; \
    _Pragma("unroll") \
    for (int c = t; c < 640; c += 256) { \
        int mat = c >= 320 ? 1 : 0; int cc = c - mat * 320; \
        int m = cc >> 2, ch = cc & 3; \
        const __nv_bfloat16* g = (mat ? g_J_lo : g_J_hi) + (size_t)(m0 + m) * 2048 + k0 + ch * 8; \
        cpa16(s + mat * ASLb + (uint32_t)((m * 40 + ch * 8) * 2), g); \
    } \
    _Pragma("unroll") \
    for (int c = t; c < 1024; c += 256) { \
        int mat = c >= 512 ? 1 : 0; int cc = c - mat * 512; \
        int k = cc >> 4, ch = cc & 15; \
        const __nv_bfloat16* g = (mat ? g_w0_lo : g_w0_hi) + (size_t)(k0 + k) * HH + n0 + ch * 8; \
        cpa16(s + (mat ? BSLb : BSHb) + (uint32_t)((k * 136 + ch * 8) * 2), g); \
    } \
    CP_COMMIT(); } while (0)

#define M_COMPUTE(STG) do { \
    uint32_t ab = sb + (STG) * STGb; \
    _Pragma("unroll") \
    for (int ks = 0; ks < 2; ks++) { \
        uint32_t ah[5][4], al[5][4], bh[2][2], bl[2][2]; \
        int ar  = lane & 15; \
        int acf = ks * 16 + ((lane >> 4) << 3); \
        _Pragma("unroll") \
        for (int i = 0; i < 5; i++) { \
            uint32_t off = (uint32_t)(((i * 16 + ar) * 40 + acf) * 2); \
            ldsm4(ab + off, ah[i]); \
            ldsm4(ab + ASLb + off, al[i]); \
        } \
        int br  = ks * 16 + (lane & 15); \
        int bcf = (lane >> 4) << 3; \
        uint32_t boff = (uint32_t)((br * 136 + wn + bcf) * 2); \
        ldsm4t(ab + BSHb + boff, bh[0], bh[1]); \
        ldsm4t(ab + BSLb + boff, bl[0], bl[1]); \
        _Pragma("unroll") \
        for (int i = 0; i < 5; i++) \
            _Pragma("unroll") \
            for (int j = 0; j < 2; j++) { \
                MMA(acc[i][j], ah[i], bh[j]); \
                MMA(acc[i][j], ah[i], bl[j]); \
                MMA(acc[i][j], al[i], bh[j]); \
            } \
    } } while (0)

    M_PREFETCH(0, 0);
    M_PREFETCH(1, 1);

    int stg = 0;
    for (int kt = 0; kt < 64; kt++) {
        if (kt + 1 < 64) { CP_WAIT(1); } else { CP_WAIT(0); }
        __syncthreads();
        if (kt + 2 < 64) {
            int ns = stg + 2; if (ns >= 3) ns -= 3;
            M_PREFETCH(kt + 2, ns);
        }
        M_COMPUTE(stg);
        stg++; if (stg == 3) stg = 0;
    }

    int g = lane >> 2, tig = lane & 3;
#pragma unroll
    for (int i = 0; i < 5; i++)
#pragma unroll
        for (int j = 0; j < 2; j++) {
            int n = n0 + wn + j * 8 + tig * 2;
#pragma unroll
            for (int half = 0; half < 2; half++) {
                int row = m0 + i * 16 + g + half * 8;
                int bb = row / QQ;
                float v0 = fmaxf(acc[i][j][half * 2 + 0] + g_txtctrb[bb * HH + n], 0.f);
                float v1 = fmaxf(acc[i][j][half * 2 + 1] + g_txtctrb[bb * HH + n + 1], 0.f);
                float2 v; v.x = v0; v.y = v1;
                *(float2*)&g_hidden[(size_t)row * HH + n] = v;
            }
        }
#undef M_PREFETCH
#undef M_COMPUTE
}

// ---------------- MLP1 + state update + output ----------------
__global__ void k_mlp1(const float* __restrict__ m1w, const float* __restrict__ m1b,
                       float* __restrict__ out, int pass, int last) {
    int r = blockIdx.x, t = threadIdx.x;
    const float* hrow = g_hidden + (size_t)r * HH;
    float a0 = 0.f, a1 = 0.f;
    for (int h = t; h < HH; h += 256) {
        float x = hrow[h];
        a0 += x * m1w[h * 2 + 0];
        a1 += x * m1w[h * 2 + 1];
    }
    __shared__ float s0[256], s1[256];
    s0[t] = a0; s1[t] = a1; __syncthreads();
    for (int ofs = 128; ofs > 0; ofs >>= 1) {
        if (t < ofs) { s0[t] += s0[t + ofs]; s1[t] += s1[t + ofs]; }
        __syncthreads();
    }
    if (t == 0) {
        float d0 = tanhf(s0[0] + m1b[0]) * MAX_DELTA_C;
        float d1 = tanhf(s1[0] + m1b[1]) * MAX_DELTA_C;
        float s = fminf(fmaxf(g_state[r * 2 + 0] + d0, 0.f), 1.f);
        float e = fminf(fmaxf(g_state[r * 2 + 1] + d1, 0.f), 1.f);
        g_state[r * 2 + 0] = s;
        g_state[r * 2 + 1] = e;
        float c = 0.5f * (s + e);
        float w = fmaxf(e - s, 1e-6f);
        int base = (1 + pass) * BB * QQ * 2;
        out[base + r * 2 + 0] = c;
        out[base + r * 2 + 1] = w;
        if (pass == last) {
            out[r * 2 + 0] = c;
            out[r * 2 + 1] = w;
        }
    }
}

extern "C" void kernel_launch(void* const* d_in, const int* in_sizes, int n_in,
                              void* d_out, int out_size) {
    const float* pred = (const float*)d_in[0];
    const float* vid  = (const float*)d_in[1];
    const float* mask = (const float*)d_in[2];
    const float* txt  = (const float*)d_in[3];
    const float* ls   = (const float*)d_in[4];
    const float* le   = (const float*)d_in[5];
    const float* sws  = (const float*)d_in[6];
    const float* swe  = (const float*)d_in[7];
    const float* tpw  = (const float*)d_in[8];
    const float* tpb  = (const float*)d_in[9];
    const float* m0w  = (const float*)d_in[10];
    const float* m0b  = (const float*)d_in[11];
    const float* m1w  = (const float*)d_in[12];
    const float* m1b  = (const float*)d_in[13];
    float* out = (float*)d_out;

    cudaFuncSetAttribute(k_pool_mma, cudaFuncAttributeMaxDynamicSharedMemorySize, POOL_SMEM);
    cudaFuncSetAttribute(k_mlp0_mma, cudaFuncAttributeMaxDynamicSharedMemorySize, MLP0_SMEM);

    k_cvt_w0<<<(2 * HH * HH / 4) / 256, 256>>>(m0w);
    k_txt_off<<<BB, 256>>>(txt, tpw, tpb);
    k_txt_ctrb<<<dim3(HH / 256, BB, 4), 256>>>(txt, m0w);
    k_ctrb_reduce<<<(BB * HH) / 256, 256>>>(m0b);
    k_init<<<(BB * QQ + 255) / 256, 256>>>(pred);

    for (int p = 0; p < 2; p++) {
        k_weights<<<BB * QQ, 256>>>(mask, ls, le, sws, swe);
        k_pool_mma<<<dim3(HH / 128, BB), 256, POOL_SMEM>>>(vid);
        k_mlp0_mma<<<dim3(HH / 128, (BB * QQ) / 80), 256, MLP0_SMEM>>>();
        k_mlp1<<<BB * QQ, 256>>>(m1w, m1b, out, p, 1);
    }
}

// round 5
// speedup vs baseline: 6.2856x; 1.5568x over previous
#include <cuda_runtime.h>
#include <cuda_fp16.h>
#include <math.h>
#include <stdint.h>

#define BB 32
#define QQ 40
#define LL 1024
#define HH 1024
#define MIN_SIG (1.0f/4096.0f)
#define HALF_LOG_RANGE 4.9999975e-07f
#define MAX_DELTA_C 0.1f

// per-stage smem (halves): A 80*40 @0, B 32*136 @3200 ; stage = 7552 halves = 15104 B
#define A_OFFb 0
#define B_OFFb 6400
#define STG_B  15104
#define GEMM_SMEM (3 * STG_B)

// -------- device scratch --------
__device__ __half g_vid16[BB * LL * HH];
__device__ __half g_w016[2 * HH * HH];
__device__ __half g_W16[BB * 80 * LL];
__device__ __half g_J16[BB * QQ * 2 * HH];
__device__ float g_hidden[BB * QQ * HH];
__device__ float g_state[BB * QQ * 2];
__device__ float g_txtoff[BB * 2];
__device__ float g_txtctrb[BB * HH];
__device__ float g_ctrb_part[4][BB * HH];

// ---------------- helpers ----------------
__device__ __forceinline__ uint32_t s2u(const void* p) {
    return (uint32_t)__cvta_generic_to_shared(p);
}
__device__ __forceinline__ void ldsm4(uint32_t addr, uint32_t* r) {
    asm volatile("ldmatrix.sync.aligned.m8n8.x4.shared.b16 {%0,%1,%2,%3}, [%4];"
        : "=r"(r[0]), "=r"(r[1]), "=r"(r[2]), "=r"(r[3]) : "r"(addr));
}
__device__ __forceinline__ void ldsm4t(uint32_t addr, uint32_t* r01, uint32_t* r23) {
    asm volatile("ldmatrix.sync.aligned.m8n8.x4.trans.shared.b16 {%0,%1,%2,%3}, [%4];"
        : "=r"(r01[0]), "=r"(r01[1]), "=r"(r23[0]), "=r"(r23[1]) : "r"(addr));
}
__device__ __forceinline__ void cpa16(uint32_t d, const void* g) {
    asm volatile("cp.async.cg.shared.global [%0], [%1], 16;" :: "r"(d), "l"(g));
}
#define CP_COMMIT() asm volatile("cp.async.commit_group;")
#define CP_WAIT(N)  asm volatile("cp.async.wait_group %0;" :: "n"(N))

#define MMA(c, a, b) asm volatile( \
    "mma.sync.aligned.m16n8k16.row.col.f32.f16.f16.f32 " \
    "{%0,%1,%2,%3}, {%4,%5,%6,%7}, {%8,%9}, {%0,%1,%2,%3};\n" \
    : "+f"((c)[0]), "+f"((c)[1]), "+f"((c)[2]), "+f"((c)[3]) \
    : "r"((a)[0]), "r"((a)[1]), "r"((a)[2]), "r"((a)[3]), \
      "r"((b)[0]), "r"((b)[1]))

__device__ __forceinline__ uint32_t packh2(float a, float b) {
    __half2 v; v.x = __float2half(a); v.y = __float2half(b);
    return *(uint32_t*)&v;
}

// ---------------- conversions ----------------
__global__ void k_cvt_vid(const float* __restrict__ src) {
    int i = blockIdx.x * 256 + threadIdx.x;
    float4 v = ((const float4*)src)[i];
    ((uint2*)g_vid16)[i] = make_uint2(packh2(v.x, v.y), packh2(v.z, v.w));
}
__global__ void k_cvt_w0(const float* __restrict__ src) {
    int i = blockIdx.x * 256 + threadIdx.x;
    float4 v = ((const float4*)src)[i];
    ((uint2*)g_w016)[i] = make_uint2(packh2(v.x, v.y), packh2(v.z, v.w));
}

// ---------------- txt offset ----------------
__global__ void k_txt_off(const float* __restrict__ txt_rep,
                          const float* __restrict__ tpw,
                          const float* __restrict__ tpb) {
    int b = blockIdx.x, t = threadIdx.x;
    float a0 = 0.f, a1 = 0.f;
    for (int h = t; h < HH; h += 256) {
        float x = txt_rep[b * HH + h];
        a0 += x * tpw[h * 2 + 0];
        a1 += x * tpw[h * 2 + 1];
    }
    __shared__ float s0[256], s1[256];
    s0[t] = a0; s1[t] = a1; __syncthreads();
    for (int ofs = 128; ofs > 0; ofs >>= 1) {
        if (t < ofs) { s0[t] += s0[t + ofs]; s1[t] += s1[t + ofs]; }
        __syncthreads();
    }
    if (t == 0) {
        g_txtoff[b * 2 + 0] = tanhf(s0[0] + tpb[0]) * HALF_LOG_RANGE;
        g_txtoff[b * 2 + 1] = tanhf(s1[0] + tpb[1]) * HALF_LOG_RANGE;
    }
}

// ---------------- txt contribution to mlp0 ----------------
__global__ void k_txt_ctrb(const float* __restrict__ txt_rep,
                           const float* __restrict__ m0w) {
    int b = blockIdx.y;
    int ks = blockIdx.z;
    int h = blockIdx.x * 256 + threadIdx.x;
    const float* wp = m0w + (size_t)2 * HH * HH + h;
    const float* xr = txt_rep + (size_t)b * HH;
    float acc = 0.f;
    int k0 = ks * 256;
#pragma unroll 16
    for (int k = k0; k < k0 + 256; k++) acc += xr[k] * wp[(size_t)k * HH];
    g_ctrb_part[ks][b * HH + h] = acc;
}
__global__ void k_ctrb_reduce(const float* __restrict__ m0b) {
    int i = blockIdx.x * 256 + threadIdx.x;
    int h = i & (HH - 1);
    g_txtctrb[i] = g_ctrb_part[0][i] + g_ctrb_part[1][i] +
                   g_ctrb_part[2][i] + g_ctrb_part[3][i] + m0b[h];
}

// ---------------- init ----------------
__global__ void k_init(const float* __restrict__ pred) {
    int r = blockIdx.x * blockDim.x + threadIdx.x;
    if (r < BB * QQ) {
        float c = pred[r * 2 + 0], w = pred[r * 2 + 1];
        g_state[r * 2 + 0] = fminf(fmaxf(c - 0.5f * w, 0.f), 1.f);
        g_state[r * 2 + 1] = fminf(fmaxf(c + 0.5f * w, 0.f), 1.f);
    }
}

// ---------------- gaussian weights -> fp16 ----------------
__global__ void k_weights(const float* __restrict__ vid_mask,
                          const float* __restrict__ ls_p, const float* __restrict__ le_p,
                          const float* __restrict__ sws_p, const float* __restrict__ swe_p) {
    int r = blockIdx.x;
    int b = r / QQ;
    int t = threadIdx.x;
    float s = g_state[r * 2 + 0], e = g_state[r * 2 + 1];
    float width = fmaxf(e - s, 1e-6f);
    float sig_s = fmaxf(expf(ls_p[0] + sws_p[0] * width + g_txtoff[b * 2 + 0]), MIN_SIG);
    float sig_e = fmaxf(expf(le_p[0] + swe_p[0] * width + g_txtoff[b * 2 + 1]), MIN_SIG);
    float inv_ss = 1.0f / sig_s, inv_se = 1.0f / sig_e;

    const float* mrow = vid_mask + (size_t)b * LL;
    float ws[4], we[4];
    float sum_s = 0.f, sum_e = 0.f;
#pragma unroll
    for (int i = 0; i < 4; i++) {
        int l = t + i * 256;
        float tp = (float)l * (1.0f / 1023.0f);
        float m = mrow[l];
        float ds = (tp - s) * inv_ss;
        float vs = expf(-0.5f * ds * ds) * m;
        float de = (tp - e) * inv_se;
        float ve = expf(-0.5f * de * de) * m;
        ws[i] = vs; we[i] = ve;
        sum_s += vs; sum_e += ve;
    }
    __shared__ float r0[256], r1[256];
    r0[t] = sum_s; r1[t] = sum_e; __syncthreads();
    for (int ofs = 128; ofs > 0; ofs >>= 1) {
        if (t < ofs) { r0[t] += r0[t + ofs]; r1[t] += r1[t + ofs]; }
        __syncthreads();
    }
    float is = 1.0f / fmaxf(r0[0], 1e-8f);
    float ie = 1.0f / fmaxf(r1[0], 1e-8f);
    size_t rs = (size_t)(r * 2 + 0) * LL;
    size_t re = (size_t)(r * 2 + 1) * LL;
#pragma unroll
    for (int i = 0; i < 4; i++) {
        int l = t + i * 256;
        g_W16[rs + l] = __float2half(ws[i] * is);
        g_W16[re + l] = __float2half(we[i] * ie);
    }
}

// ======== shared GEMM compute macro: 80x128 tile, 5x2 warp-frag, fp16 single ========
#define TILE_COMPUTE(SBASE) do { \
    _Pragma("unroll") \
    for (int ks = 0; ks < 2; ks++) { \
        uint32_t ah[5][4], bh[2][2]; \
        int ar  = lane & 15; \
        int acf = ks * 16 + ((lane >> 4) << 3); \
        _Pragma("unroll") \
        for (int i = 0; i < 5; i++) \
            ldsm4((SBASE) + A_OFFb + (uint32_t)(((i * 16 + ar) * 40 + acf) * 2), ah[i]); \
        int br  = ks * 16 + (lane & 15); \
        int bcf = (lane >> 4) << 3; \
        ldsm4t((SBASE) + B_OFFb + (uint32_t)((br * 136 + wn + bcf) * 2), bh[0], bh[1]); \
        _Pragma("unroll") \
        for (int i = 0; i < 5; i++) \
            _Pragma("unroll") \
            for (int j = 0; j < 2; j++) \
                MMA(acc[i][j], ah[i], bh[j]); \
    } } while (0)

// prefetch one k-tile: A 80x32 (320 16B-chunks), B 32x128 (512 16B-chunks)
#define TILE_PREFETCH(Aptr, Astride, Bptr, Bstride, K0, STG) do { \
    uint32_t s = sb + (STG) * STG_B; \
    _Pragma("unroll") \
    for (int c = t; c < 320; c += 256) { \
        int m = c >> 2, ch = c & 3; \
        cpa16(s + A_OFFb + (uint32_t)((m * 40 + ch * 8) * 2), \
              (Aptr) + (size_t)m * (Astride) + (K0) + ch * 8); \
    } \
    _Pragma("unroll") \
    for (int c = t; c < 512; c += 256) { \
        int k = c >> 4, ch = c & 15; \
        cpa16(s + B_OFFb + (uint32_t)((k * 136 + ch * 8) * 2), \
              (Bptr) + (size_t)((K0) + k) * (Bstride) + ch * 8); \
    } \
    CP_COMMIT(); } while (0)

// ---------------- pool GEMM: C[b](80,1024) = W[b](80,1024) @ V16[b](1024,1024) ----------------
__global__ void __launch_bounds__(256) k_pool_mma() {
    extern __shared__ __half dsm[];
    int b  = blockIdx.y;
    int n0 = blockIdx.x * 128;
    const __half* Ag = g_W16 + (size_t)b * 80 * LL;
    const __half* Bg = g_vid16 + (size_t)b * LL * HH + n0;

    int t = threadIdx.x;
    int lane = t & 31, wid = t >> 5;
    int wn = wid * 16;
    uint32_t sb = s2u(dsm);

    float acc[5][2][4];
#pragma unroll
    for (int i = 0; i < 5; i++)
#pragma unroll
        for (int j = 0; j < 2; j++)
#pragma unroll
            for (int c = 0; c < 4; c++) acc[i][j][c] = 0.f;

    TILE_PREFETCH(Ag, LL, Bg, HH, 0, 0);
    TILE_PREFETCH(Ag, LL, Bg, HH, 32, 1);

    int stg = 0;
    for (int kt = 0; kt < 32; kt++) {
        if (kt + 1 < 32) { CP_WAIT(1); } else { CP_WAIT(0); }
        __syncthreads();
        if (kt + 2 < 32) {
            int ns = stg + 2; if (ns >= 3) ns -= 3;
            TILE_PREFETCH(Ag, LL, Bg, HH, (kt + 2) * 32, ns);
        }
        TILE_COMPUTE(sb + stg * STG_B);
        stg++; if (stg == 3) stg = 0;
    }

    // epilogue -> J fp16, joint layout: row b*40+q, col (m&1)*1024 + n
    int g = lane >> 2, tig = lane & 3;
#pragma unroll
    for (int i = 0; i < 5; i++)
#pragma unroll
        for (int j = 0; j < 2; j++) {
            int n = n0 + wn + j * 8 + tig * 2;
#pragma unroll
            for (int half = 0; half < 2; half++) {
                int m = i * 16 + g + half * 8;
                int jr  = b * QQ + (m >> 1);
                int col = (m & 1) * HH + n;
                *(uint32_t*)&g_J16[(size_t)jr * 2048 + col] =
                    packh2(acc[i][j][half * 2 + 0], acc[i][j][half * 2 + 1]);
            }
        }
}

// ---------------- MLP0 GEMM: hidden(1280,1024) = relu(J(1280,2048)@w0 + ctrb) ----------------
__global__ void __launch_bounds__(256) k_mlp0_mma() {
    extern __shared__ __half dsm[];
    int m0 = blockIdx.y * 80;
    int n0 = blockIdx.x * 128;
    const __half* Ag = g_J16 + (size_t)m0 * 2048;
    const __half* Bg = g_w016 + n0;

    int t = threadIdx.x;
    int lane = t & 31, wid = t >> 5;
    int wn = wid * 16;
    uint32_t sb = s2u(dsm);

    float acc[5][2][4];
#pragma unroll
    for (int i = 0; i < 5; i++)
#pragma unroll
        for (int j = 0; j < 2; j++)
#pragma unroll
            for (int c = 0; c < 4; c++) acc[i][j][c] = 0.f;

    TILE_PREFETCH(Ag, 2048, Bg, HH, 0, 0);
    TILE_PREFETCH(Ag, 2048, Bg, HH, 32, 1);

    int stg = 0;
    for (int kt = 0; kt < 64; kt++) {
        if (kt + 1 < 64) { CP_WAIT(1); } else { CP_WAIT(0); }
        __syncthreads();
        if (kt + 2 < 64) {
            int ns = stg + 2; if (ns >= 3) ns -= 3;
            TILE_PREFETCH(Ag, 2048, Bg, HH, (kt + 2) * 32, ns);
        }
        TILE_COMPUTE(sb + stg * STG_B);
        stg++; if (stg == 3) stg = 0;
    }

    int g = lane >> 2, tig = lane & 3;
#pragma unroll
    for (int i = 0; i < 5; i++)
#pragma unroll
        for (int j = 0; j < 2; j++) {
            int n = n0 + wn + j * 8 + tig * 2;
#pragma unroll
            for (int half = 0; half < 2; half++) {
                int row = m0 + i * 16 + g + half * 8;
                int bb = row / QQ;
                float v0 = fmaxf(acc[i][j][half * 2 + 0] + g_txtctrb[bb * HH + n], 0.f);
                float v1 = fmaxf(acc[i][j][half * 2 + 1] + g_txtctrb[bb * HH + n + 1], 0.f);
                float2 v; v.x = v0; v.y = v1;
                *(float2*)&g_hidden[(size_t)row * HH + n] = v;
            }
        }
}

// ---------------- MLP1 + state update + output ----------------
__global__ void k_mlp1(const float* __restrict__ m1w, const float* __restrict__ m1b,
                       float* __restrict__ out, int pass, int last) {
    int r = blockIdx.x, t = threadIdx.x;
    const float* hrow = g_hidden + (size_t)r * HH;
    float a0 = 0.f, a1 = 0.f;
    for (int h = t; h < HH; h += 256) {
        float x = hrow[h];
        a0 += x * m1w[h * 2 + 0];
        a1 += x * m1w[h * 2 + 1];
    }
    __shared__ float s0[256], s1[256];
    s0[t] = a0; s1[t] = a1; __syncthreads();
    for (int ofs = 128; ofs > 0; ofs >>= 1) {
        if (t < ofs) { s0[t] += s0[t + ofs]; s1[t] += s1[t + ofs]; }
        __syncthreads();
    }
    if (t == 0) {
        float d0 = tanhf(s0[0] + m1b[0]) * MAX_DELTA_C;
        float d1 = tanhf(s1[0] + m1b[1]) * MAX_DELTA_C;
        float s = fminf(fmaxf(g_state[r * 2 + 0] + d0, 0.f), 1.f);
        float e = fminf(fmaxf(g_state[r * 2 + 1] + d1, 0.f), 1.f);
        g_state[r * 2 + 0] = s;
        g_state[r * 2 + 1] = e;
        float c = 0.5f * (s + e);
        float w = fmaxf(e - s, 1e-6f);
        int base = (1 + pass) * BB * QQ * 2;
        out[base + r * 2 + 0] = c;
        out[base + r * 2 + 1] = w;
        if (pass == last) {
            out[r * 2 + 0] = c;
            out[r * 2 + 1] = w;
        }
    }
}

extern "C" void kernel_launch(void* const* d_in, const int* in_sizes, int n_in,
                              void* d_out, int out_size) {
    const float* pred = (const float*)d_in[0];
    const float* vid  = (const float*)d_in[1];
    const float* mask = (const float*)d_in[2];
    const float* txt  = (const float*)d_in[3];
    const float* ls   = (const float*)d_in[4];
    const float* le   = (const float*)d_in[5];
    const float* sws  = (const float*)d_in[6];
    const float* swe  = (const float*)d_in[7];
    const float* tpw  = (const float*)d_in[8];
    const float* tpb  = (const float*)d_in[9];
    const float* m0w  = (const float*)d_in[10];
    const float* m0b  = (const float*)d_in[11];
    const float* m1w  = (const float*)d_in[12];
    const float* m1b  = (const float*)d_in[13];
    float* out = (float*)d_out;

    cudaFuncSetAttribute(k_pool_mma, cudaFuncAttributeMaxDynamicSharedMemorySize, GEMM_SMEM);
    cudaFuncSetAttribute(k_mlp0_mma, cudaFuncAttributeMaxDynamicSharedMemorySize, GEMM_SMEM);

    k_cvt_vid<<<(BB * LL * HH / 4) / 256, 256>>>(vid);
    k_cvt_w0<<<(2 * HH * HH / 4) / 256, 256>>>(m0w);
    k_txt_off<<<BB, 256>>>(txt, tpw, tpb);
    k_txt_ctrb<<<dim3(HH / 256, BB, 4), 256>>>(txt, m0w);
    k_ctrb_reduce<<<(BB * HH) / 256, 256>>>(m0b);
    k_init<<<(BB * QQ + 255) / 256, 256>>>(pred);

    for (int p = 0; p < 2; p++) {
        k_weights<<<BB * QQ, 256>>>(mask, ls, le, sws, swe);
        k_pool_mma<<<dim3(HH / 128, BB), 256, GEMM_SMEM>>>();
        k_mlp0_mma<<<dim3(HH / 128, (BB * QQ) / 80), 256, GEMM_SMEM>>>();
        k_mlp1<<<BB * QQ, 256>>>(m1w, m1b, out, p, 1);
    }
}

// round 7
// speedup vs baseline: 6.6858x; 1.0637x over previous
#include <cuda_runtime.h>
#include <cuda_fp16.h>
#include <math.h>
#include <stdint.h>

#define BB 32
#define QQ 40
#define LL 1024
#define HH 1024
#define MIN_SIG (1.0f/4096.0f)
#define HALF_LOG_RANGE 4.9999975e-07f
#define MAX_DELTA_C 0.1f

// per-stage smem (bytes): A 80*40 halves @0 (6400B), B 32*136 halves @6400 (8704B); stage 15104B
#define A_OFFb 0
#define B_OFFb 6400
#define STG_B  15104
#define GEMM_SMEM (3 * STG_B)

// -------- device scratch --------
__device__ __half g_w016[2 * HH * HH];
__device__ __half g_W16[BB * 80 * LL];
__device__ __half g_J16[BB * QQ * 2 * HH];
__device__ float g_hidden[BB * QQ * HH];
__device__ float g_state[BB * QQ * 2];
__device__ float g_txtoff[BB * 2];
__device__ float g_txtctrb[BB * HH];
__device__ float g_ctrb_part[16][BB * HH];

// ---------------- helpers ----------------
__device__ __forceinline__ uint32_t s2u(const void* p) {
    return (uint32_t)__cvta_generic_to_shared(p);
}
__device__ __forceinline__ void ldsm4(uint32_t addr, uint32_t* r) {
    asm volatile("ldmatrix.sync.aligned.m8n8.x4.shared.b16 {%0,%1,%2,%3}, [%4];"
        : "=r"(r[0]), "=r"(r[1]), "=r"(r[2]), "=r"(r[3]) : "r"(addr));
}
__device__ __forceinline__ void ldsm4t(uint32_t addr, uint32_t* r01, uint32_t* r23) {
    asm volatile("ldmatrix.sync.aligned.m8n8.x4.trans.shared.b16 {%0,%1,%2,%3}, [%4];"
        : "=r"(r01[0]), "=r"(r01[1]), "=r"(r23[0]), "=r"(r23[1]) : "r"(addr));
}
__device__ __forceinline__ void cpa16(uint32_t d, const void* g) {
    asm volatile("cp.async.cg.shared.global [%0], [%1], 16;" :: "r"(d), "l"(g));
}
#define CP_COMMIT() asm volatile("cp.async.commit_group;")
#define CP_WAIT(N)  asm volatile("cp.async.wait_group %0;" :: "n"(N))

#define MMA(c, a, b) asm volatile( \
    "mma.sync.aligned.m16n8k16.row.col.f32.f16.f16.f32 " \
    "{%0,%1,%2,%3}, {%4,%5,%6,%7}, {%8,%9}, {%0,%1,%2,%3};\n" \
    : "+f"((c)[0]), "+f"((c)[1]), "+f"((c)[2]), "+f"((c)[3]) \
    : "r"((a)[0]), "r"((a)[1]), "r"((a)[2]), "r"((a)[3]), \
      "r"((b)[0]), "r"((b)[1]))

__device__ __forceinline__ uint32_t packh2(float a, float b) {
    __half2 v; v.x = __float2half(a); v.y = __float2half(b);
    return *(uint32_t*)&v;
}

// ---------------- w0 fp16 conversion ----------------
__global__ void k_cvt_w0(const float* __restrict__ src) {
    int i = blockIdx.x * 256 + threadIdx.x;
    float4 v = ((const float4*)src)[i];
    ((uint2*)g_w016)[i] = make_uint2(packh2(v.x, v.y), packh2(v.z, v.w));
}

// ---------------- txt offset ----------------
__global__ void k_txt_off(const float* __restrict__ txt_rep,
                          const float* __restrict__ tpw,
                          const float* __restrict__ tpb) {
    int b = blockIdx.x, t = threadIdx.x;
    float a0 = 0.f, a1 = 0.f;
    for (int h = t; h < HH; h += 256) {
        float x = txt_rep[b * HH + h];
        a0 += x * tpw[h * 2 + 0];
        a1 += x * tpw[h * 2 + 1];
    }
    __shared__ float s0[256], s1[256];
    s0[t] = a0; s1[t] = a1; __syncthreads();
    for (int ofs = 128; ofs > 0; ofs >>= 1) {
        if (t < ofs) { s0[t] += s0[t + ofs]; s1[t] += s1[t + ofs]; }
        __syncthreads();
    }
    if (t == 0) {
        g_txtoff[b * 2 + 0] = tanhf(s0[0] + tpb[0]) * HALF_LOG_RANGE;
        g_txtoff[b * 2 + 1] = tanhf(s1[0] + tpb[1]) * HALF_LOG_RANGE;
    }
}

// ---------------- txt contribution: weight-stationary ----------------
// grid (8 h-tiles, 16 k-tiles); each block serves all 32 batches; weights read once.
__global__ void k_txt_ctrb(const float* __restrict__ txt_rep,
                           const float* __restrict__ m0w) {
    __shared__ float st[32][64];
    int h0 = blockIdx.x * 128, k0 = blockIdx.y * 64;
    int t = threadIdx.x;
#pragma unroll
    for (int i = 0; i < 8; i++) {
        int idx = t + i * 256;
        int b = idx >> 6, k = idx & 63;
        st[b][k] = txt_rep[b * HH + k0 + k];
    }
    __syncthreads();
    int tx = t & 63;          // h pair: h = h0 + tx*2
    int ty = t >> 6;          // batch group of 8
    float acc[8][2];
#pragma unroll
    for (int i = 0; i < 8; i++) { acc[i][0] = 0.f; acc[i][1] = 0.f; }
    const float* wbase = m0w + (size_t)(2 * HH + k0) * HH + h0 + tx * 2;
#pragma unroll 4
    for (int k = 0; k < 64; k++) {
        float2 w = *(const float2*)(wbase + (size_t)k * HH);
#pragma unroll
        for (int i = 0; i < 8; i++) {
            float x = st[ty * 8 + i][k];
            acc[i][0] += x * w.x;
            acc[i][1] += x * w.y;
        }
    }
    float* part = g_ctrb_part[blockIdx.y];
#pragma unroll
    for (int i = 0; i < 8; i++) {
        float2 v; v.x = acc[i][0]; v.y = acc[i][1];
        *(float2*)&part[(ty * 8 + i) * HH + h0 + tx * 2] = v;
    }
}

__global__ void k_ctrb_reduce(const float* __restrict__ m0b) {
    int i = blockIdx.x * 256 + threadIdx.x;
    int h = i & (HH - 1);
    float a = m0b[h];
#pragma unroll
    for (int p = 0; p < 16; p++) a += g_ctrb_part[p][i];
    g_txtctrb[i] = a;
}

// ---------------- init ----------------
__global__ void k_init(const float* __restrict__ pred) {
    int r = blockIdx.x * blockDim.x + threadIdx.x;
    if (r < BB * QQ) {
        float c = pred[r * 2 + 0], w = pred[r * 2 + 1];
        g_state[r * 2 + 0] = fminf(fmaxf(c - 0.5f * w, 0.f), 1.f);
        g_state[r * 2 + 1] = fminf(fmaxf(c + 0.5f * w, 0.f), 1.f);
    }
}

// ---------------- gaussian weights -> fp16 ----------------
__global__ void k_weights(const float* __restrict__ vid_mask,
                          const float* __restrict__ ls_p, const float* __restrict__ le_p,
                          const float* __restrict__ sws_p, const float* __restrict__ swe_p) {
    int r = blockIdx.x;
    int b = r / QQ;
    int t = threadIdx.x;
    float s = g_state[r * 2 + 0], e = g_state[r * 2 + 1];
    float width = fmaxf(e - s, 1e-6f);
    float sig_s = fmaxf(expf(ls_p[0] + sws_p[0] * width + g_txtoff[b * 2 + 0]), MIN_SIG);
    float sig_e = fmaxf(expf(le_p[0] + swe_p[0] * width + g_txtoff[b * 2 + 1]), MIN_SIG);
    float inv_ss = 1.0f / sig_s, inv_se = 1.0f / sig_e;

    const float* mrow = vid_mask + (size_t)b * LL;
    float ws[4], we[4];
    float sum_s = 0.f, sum_e = 0.f;
#pragma unroll
    for (int i = 0; i < 4; i++) {
        int l = t + i * 256;
        float tp = (float)l * (1.0f / 1023.0f);
        float m = mrow[l];
        float ds = (tp - s) * inv_ss;
        float vs = expf(-0.5f * ds * ds) * m;
        float de = (tp - e) * inv_se;
        float ve = expf(-0.5f * de * de) * m;
        ws[i] = vs; we[i] = ve;
        sum_s += vs; sum_e += ve;
    }
    __shared__ float r0[256], r1[256];
    r0[t] = sum_s; r1[t] = sum_e; __syncthreads();
    for (int ofs = 128; ofs > 0; ofs >>= 1) {
        if (t < ofs) { r0[t] += r0[t + ofs]; r1[t] += r1[t + ofs]; }
        __syncthreads();
    }
    float is = 1.0f / fmaxf(r0[0], 1e-8f);
    float ie = 1.0f / fmaxf(r1[0], 1e-8f);
    size_t rs = (size_t)(r * 2 + 0) * LL;
    size_t re = (size_t)(r * 2 + 1) * LL;
#pragma unroll
    for (int i = 0; i < 4; i++) {
        int l = t + i * 256;
        g_W16[rs + l] = __float2half(ws[i] * is);
        g_W16[re + l] = __float2half(we[i] * ie);
    }
}

// ======== shared GEMM compute macro: 80x128 tile, 5x2 warp-frag ========
#define TILE_COMPUTE(SBASE) do { \
    _Pragma("unroll") \
    for (int ks = 0; ks < 2; ks++) { \
        uint32_t ah[5][4], bh[2][2]; \
        int ar  = lane & 15; \
        int acf = ks * 16 + ((lane >> 4) << 3); \
        _Pragma("unroll") \
        for (int i = 0; i < 5; i++) \
            ldsm4((SBASE) + A_OFFb + (uint32_t)(((i * 16 + ar) * 40 + acf) * 2), ah[i]); \
        int br  = ks * 16 + (lane & 15); \
        int bcf = (lane >> 4) << 3; \
        ldsm4t((SBASE) + B_OFFb + (uint32_t)((br * 136 + wn + bcf) * 2), bh[0], bh[1]); \
        _Pragma("unroll") \
        for (int i = 0; i < 5; i++) \
            _Pragma("unroll") \
            for (int j = 0; j < 2; j++) \
                MMA(acc[i][j], ah[i], bh[j]); \
    } } while (0)

// ---------------- pool GEMM: C[b](80,1024) = W16[b](80,1024) @ vid_fp32(1024,1024) ------------
// Register-staged double buffer; B read fp32, converted to fp16 on smem store.
__global__ void __launch_bounds__(256) k_pool_mma(const float* __restrict__ vid) {
    __shared__ __align__(16) __half sm[2 * STG_B / 2];
    int b  = blockIdx.y;
    int n0 = blockIdx.x * 128;
    const __half* Ag = g_W16 + (size_t)b * 80 * LL;
    const float* Bv = vid + (size_t)b * LL * HH + n0;

    int t = threadIdx.x;
    int lane = t & 31, wid = t >> 5;
    int wn = wid * 16;
    uint32_t sb = s2u(sm);

    float acc[5][2][4];
#pragma unroll
    for (int i = 0; i < 5; i++)
#pragma unroll
        for (int j = 0; j < 2; j++)
#pragma unroll
            for (int c = 0; c < 4; c++) acc[i][j][c] = 0.f;

    int ar0 = t >> 2,         ac0 = (t & 3) << 3;
    int ar1 = (t + 256) >> 2, ac1 = ac0;
    bool a1v = (t < 64);
    uint4 rah0, rah1;
    float4 rb[4];

#define P_LOAD(K0) do { \
    rah0 = *(const uint4*)(Ag + (size_t)ar0 * LL + (K0) + ac0); \
    if (a1v) rah1 = *(const uint4*)(Ag + (size_t)ar1 * LL + (K0) + ac1); \
    _Pragma("unroll") \
    for (int s = 0; s < 4; s++) { \
        int idx = t + s * 256; \
        int k = idx >> 5, c4 = idx & 31; \
        rb[s] = *(const float4*)(Bv + (size_t)((K0) + k) * HH + c4 * 4); \
    } } while (0)

#define P_STORE(BUF) do { \
    __half* base = sm + (BUF) * (STG_B / 2); \
    *(uint4*)&base[ar0 * 40 + ac0] = rah0; \
    if (a1v) *(uint4*)&base[ar1 * 40 + ac1] = rah1; \
    _Pragma("unroll") \
    for (int s = 0; s < 4; s++) { \
        int idx = t + s * 256; \
        int k = idx >> 5, c4 = idx & 31; \
        *(uint2*)&base[B_OFFb / 2 + k * 136 + c4 * 4] = \
            make_uint2(packh2(rb[s].x, rb[s].y), packh2(rb[s].z, rb[s].w)); \
    } } while (0)

    P_LOAD(0);
    P_STORE(0);
    __syncthreads();

    for (int kt = 0; kt < 32; kt++) {
        if (kt + 1 < 32) P_LOAD((kt + 1) * 32);
        TILE_COMPUTE(sb + (uint32_t)(kt & 1) * STG_B);
        if (kt + 1 < 32) { P_STORE((kt + 1) & 1); __syncthreads(); }
    }

    // epilogue -> J fp16, joint layout: row b*40+q, col (m&1)*1024 + n
    int g = lane >> 2, tig = lane & 3;
#pragma unroll
    for (int i = 0; i < 5; i++)
#pragma unroll
        for (int j = 0; j < 2; j++) {
            int n = n0 + wn + j * 8 + tig * 2;
#pragma unroll
            for (int half = 0; half < 2; half++) {
                int m = i * 16 + g + half * 8;
                int jr  = b * QQ + (m >> 1);
                int col = (m & 1) * HH + n;
                *(uint32_t*)&g_J16[(size_t)jr * 2048 + col] =
                    packh2(acc[i][j][half * 2 + 0], acc[i][j][half * 2 + 1]);
            }
        }
#undef P_LOAD
#undef P_STORE
}

// ---------------- MLP0 GEMM: hidden(1280,1024) = relu(J(1280,2048)@w0 + ctrb) ----------------
// cp.async 3-stage pipeline (all operands fp16 in global)
__global__ void __launch_bounds__(256) k_mlp0_mma() {
    extern __shared__ __half dsm[];
    int m0 = blockIdx.y * 80;
    int n0 = blockIdx.x * 128;
    const __half* Ag = g_J16 + (size_t)m0 * 2048;
    const __half* Bg = g_w016 + n0;

    int t = threadIdx.x;
    int lane = t & 31, wid = t >> 5;
    int wn = wid * 16;
    uint32_t sb = s2u(dsm);

    float acc[5][2][4];
#pragma unroll
    for (int i = 0; i < 5; i++)
#pragma unroll
        for (int j = 0; j < 2; j++)
#pragma unroll
            for (int c = 0; c < 4; c++) acc[i][j][c] = 0.f;

#define M_PREFETCH(K0, STG) do { \
    uint32_t s = sb + (STG) * STG_B; \
    _Pragma("unroll") \
    for (int c = t; c < 320; c += 256) { \
        int m = c >> 2, ch = c & 3; \
        cpa16(s + A_OFFb + (uint32_t)((m * 40 + ch * 8) * 2), \
              Ag + (size_t)m * 2048 + (K0) + ch * 8); \
    } \
    _Pragma("unroll") \
    for (int c = t; c < 512; c += 256) { \
        int k = c >> 4, ch = c & 15; \
        cpa16(s + B_OFFb + (uint32_t)((k * 136 + ch * 8) * 2), \
              Bg + (size_t)((K0) + k) * HH + ch * 8); \
    } \
    CP_COMMIT(); } while (0)

    M_PREFETCH(0, 0);
    M_PREFETCH(32, 1);

    int stg = 0;
    for (int kt = 0; kt < 64; kt++) {
        if (kt + 1 < 64) { CP_WAIT(1); } else { CP_WAIT(0); }
        __syncthreads();
        if (kt + 2 < 64) {
            int ns = stg + 2; if (ns >= 3) ns -= 3;
            M_PREFETCH((kt + 2) * 32, ns);
        }
        TILE_COMPUTE(sb + (uint32_t)stg * STG_B);
        stg++; if (stg == 3) stg = 0;
    }

    int g = lane >> 2, tig = lane & 3;
#pragma unroll
    for (int i = 0; i < 5; i++)
#pragma unroll
        for (int j = 0; j < 2; j++) {
            int n = n0 + wn + j * 8 + tig * 2;
#pragma unroll
            for (int half = 0; half < 2; half++) {
                int row = m0 + i * 16 + g + half * 8;
                int bb = row / QQ;
                float v0 = fmaxf(acc[i][j][half * 2 + 0] + g_txtctrb[bb * HH + n], 0.f);
                float v1 = fmaxf(acc[i][j][half * 2 + 1] + g_txtctrb[bb * HH + n + 1], 0.f);
                float2 v; v.x = v0; v.y = v1;
                *(float2*)&g_hidden[(size_t)row * HH + n] = v;
            }
        }
#undef M_PREFETCH
}

// ---------------- MLP1 + state update + output ----------------
__global__ void k_mlp1(const float* __restrict__ m1w, const float* __restrict__ m1b,
                       float* __restrict__ out, int pass, int last) {
    int r = blockIdx.x, t = threadIdx.x;
    const float* hrow = g_hidden + (size_t)r * HH;
    float a0 = 0.f, a1 = 0.f;
    for (int h = t; h < HH; h += 256) {
        float x = hrow[h];
        a0 += x * m1w[h * 2 + 0];
        a1 += x * m1w[h * 2 + 1];
    }
    __shared__ float s0[256], s1[256];
    s0[t] = a0; s1[t] = a1; __syncthreads();
    for (int ofs = 128; ofs > 0; ofs >>= 1) {
        if (t < ofs) { s0[t] += s0[t + ofs]; s1[t] += s1[t + ofs]; }
        __syncthreads();
    }
    if (t == 0) {
        float d0 = tanhf(s0[0] + m1b[0]) * MAX_DELTA_C;
        float d1 = tanhf(s1[0] + m1b[1]) * MAX_DELTA_C;
        float s = fminf(fmaxf(g_state[r * 2 + 0] + d0, 0.f), 1.f);
        float e = fminf(fmaxf(g_state[r * 2 + 1] + d1, 0.f), 1.f);
        g_state[r * 2 + 0] = s;
        g_state[r * 2 + 1] = e;
        float c = 0.5f * (s + e);
        float w = fmaxf(e - s, 1e-6f);
        int base = (1 + pass) * BB * QQ * 2;
        out[base + r * 2 + 0] = c;
        out[base + r * 2 + 1] = w;
        if (pass == last) {
            out[r * 2 + 0] = c;
            out[r * 2 + 1] = w;
        }
    }
}

extern "C" void kernel_launch(void* const* d_in, const int* in_sizes, int n_in,
                              void* d_out, int out_size) {
    const float* pred = (const float*)d_in[0];
    const float* vid  = (const float*)d_in[1];
    const float* mask = (const float*)d_in[2];
    const float* txt  = (const float*)d_in[3];
    const float* ls   = (const float*)d_in[4];
    const float* le   = (const float*)d_in[5];
    const float* sws  = (const float*)d_in[6];
    const float* swe  = (const float*)d_in[7];
    const float* tpw  = (const float*)d_in[8];
    const float* tpb  = (const float*)d_in[9];
    const float* m0w  = (const float*)d_in[10];
    const float* m0b  = (const float*)d_in[11];
    const float* m1w  = (const float*)d_in[12];
    const float* m1b  = (const float*)d_in[13];
    float* out = (float*)d_out;

    cudaFuncSetAttribute(k_mlp0_mma, cudaFuncAttributeMaxDynamicSharedMemorySize, GEMM_SMEM);

    k_cvt_w0<<<(2 * HH * HH / 4) / 256, 256>>>(m0w);
    k_txt_off<<<BB, 256>>>(txt, tpw, tpb);
    k_txt_ctrb<<<dim3(HH / 128, 16), 256>>>(txt, m0w);
    k_ctrb_reduce<<<(BB * HH) / 256, 256>>>(m0b);
    k_init<<<(BB * QQ + 255) / 256, 256>>>(pred);

    for (int p = 0; p < 2; p++) {
        k_weights<<<BB * QQ, 256>>>(mask, ls, le, sws, swe);
        k_pool_mma<<<dim3(HH / 128, BB), 256>>>(vid);
        k_mlp0_mma<<<dim3(HH / 128, (BB * QQ) / 80), 256, GEMM_SMEM>>>();
        k_mlp1<<<BB * QQ, 256>>>(m1w, m1b, out, p, 1);
    }
}